// round 6
// baseline (speedup 1.0000x reference)
#include <cuda_runtime.h>
#include <cuda_bf16.h>
#include <math.h>
#include <stdint.h>

// ---------------- problem constants ----------------
#define BB      8
#define TT      4096
#define DD      512
#define QQ      4
#define KK_CB   1024
#define KER     5
#define TOUT    2048
#define NTOK    32768
#define NELEM   (NTOK * DD)              // 16777216
#define Y_SZ    (BB * TOUT * DD)         // 8388608
#define QO_SZ   NELEM
#define IDX_SZ  (QQ * NTOK)
#define LOSS_OFF (Y_SZ + QO_SZ + IDX_SZ)
#define KCONV   (KER * DD)               // 2560

// tile geometry: 128 rows x 32 bf16 (64B/row) per tile, 4 tiles/buffer, 2 buffers
#define TILE_B   8192
#define BUF_B    (4 * TILE_B)            // 32768
#define SMEM_DYN (2 * BUF_B)             // 65536

// ---------------- persistent scratch ----------------
__device__ float  g_residual[NELEM];
__device__ __nv_bfloat16 g_a_hi[NELEM], g_a_lo[NELEM];
__device__ __nv_bfloat16 g_q_hi[NELEM], g_q_lo[NELEM];
__device__ __nv_bfloat16 g_cb_hi[QQ*KK_CB*DD], g_cb_lo[QQ*KK_CB*DD];
__device__ __nv_bfloat16 g_wt_hi[DD*KCONV], g_wt_lo[DD*KCONV];
__device__ float  g_cnorm[QQ * KK_CB];
__device__ int    g_idx[QQ * NTOK];
__device__ float  g_d1[NTOK], g_d2[NTOK];
__device__ double g_loss;

// ---------------- helpers ----------------
__device__ __forceinline__ uint32_t smem_u32(const void* p) {
    uint32_t a;
    asm("{ .reg .u64 t; cvta.to.shared.u64 t, %1; cvt.u32.u64 %0, t; }" : "=r"(a) : "l"(p));
    return a;
}
__device__ __forceinline__ void ldsm4(uint32_t* r, uint32_t a) {
    asm volatile("ldmatrix.sync.aligned.m8n8.x4.shared.b16 {%0,%1,%2,%3}, [%4];"
                 : "=r"(r[0]), "=r"(r[1]), "=r"(r[2]), "=r"(r[3]) : "r"(a));
}
__device__ __forceinline__ void mma_bf16(float* c, const uint32_t* a, uint32_t b0, uint32_t b1) {
    asm volatile("mma.sync.aligned.m16n8k16.row.col.f32.bf16.bf16.f32 "
                 "{%0,%1,%2,%3},{%4,%5,%6,%7},{%8,%9},{%0,%1,%2,%3};"
                 : "+f"(c[0]), "+f"(c[1]), "+f"(c[2]), "+f"(c[3])
                 : "r"(a[0]), "r"(a[1]), "r"(a[2]), "r"(a[3]), "r"(b0), "r"(b1));
}
__device__ __forceinline__ void split1(float v, __nv_bfloat16& h, __nv_bfloat16& l) {
    h = __float2bfloat16(v);
    l = __float2bfloat16(v - __bfloat162float(h));
}
// swizzled offset within a 128x32 bf16 tile: row-major 64B rows, 16B chunks XOR-permuted
__device__ __forceinline__ uint32_t swz(int row, int c16) {
    return (uint32_t)(row * 64 + ((c16 ^ ((row >> 1) & 3)) << 4));
}

// ---------------- prep kernels ----------------
__global__ void cnorm_kernel(const float* __restrict__ cb) {
    if (blockIdx.x == 0 && threadIdx.x == 0) g_loss = 0.0;
    int w = (blockIdx.x * blockDim.x + threadIdx.x) >> 5;
    int lane = threadIdx.x & 31;
    if (w >= QQ * KK_CB) return;
    const float* c = cb + (size_t)w * DD;
    float s = 0.f;
    #pragma unroll
    for (int d = lane; d < DD; d += 32) { float v = c[d]; s += v * v; }
    #pragma unroll
    for (int o = 16; o > 0; o >>= 1) s += __shfl_down_sync(0xffffffffu, s, o);
    if (lane == 0) g_cnorm[w] = s;
}
__global__ void split_x_kernel(const float* __restrict__ x) {
    for (int e = blockIdx.x * blockDim.x + threadIdx.x; e < NELEM; e += gridDim.x * blockDim.x)
        split1(x[e], g_a_hi[e], g_a_lo[e]);
}
__global__ void split_cb_kernel(const float* __restrict__ cb) {
    int n = QQ * KK_CB * DD;
    for (int e = blockIdx.x * blockDim.x + threadIdx.x; e < n; e += gridDim.x * blockDim.x)
        split1(cb[e], g_cb_hi[e], g_cb_lo[e]);
}
__global__ void transpose_w_kernel(const float* __restrict__ w) {
    int n = KER * DD * DD;
    for (int e = blockIdx.x * blockDim.x + threadIdx.x; e < n; e += gridDim.x * blockDim.x) {
        int kk = e / (DD * DD);
        int r  = e - kk * DD * DD;
        int cin = r >> 9, cout = r & 511;
        int o = cout * KCONV + kk * DD + cin;
        split1(w[e], g_wt_hi[o], g_wt_lo[o]);
    }
}

// ---------------- VQ distance GEMM + argmin via mma.sync, swizzled smem ----------------
__global__ __launch_bounds__(256)
void vq_mma(int stage) {
    extern __shared__ char smem[];
    uint32_t sb = smem_u32(smem);
    int tid = threadIdx.x, lane = tid & 31, w = tid >> 5;
    int wm = w & 1, wn = w >> 1;          // 2 x 4 warp grid: 64 rows x 32 cols each
    int row0 = blockIdx.x * 128;

    const __nv_bfloat16* __restrict__ Bh = g_cb_hi + (size_t)stage * KK_CB * DD;
    const __nv_bfloat16* __restrict__ Bl = g_cb_lo + (size_t)stage * KK_CB * DD;
    const float* __restrict__ cn = g_cnorm + stage * KK_CB;

    // loader mapping: 2 chunks per tile per thread
    int lr0 = tid >> 2,        lc0 = tid & 3;
    int lr1 = (tid + 256) >> 2, lc1 = (tid + 256) & 3;
    uint32_t so0 = swz(lr0, lc0), so1 = swz(lr1, lc1);

    // fragment address components
    int hi16 = (lane >> 4) & 1;
    int rA[4], rB[2];
    #pragma unroll
    for (int mf = 0; mf < 4; mf++) rA[mf] = wm * 64 + mf * 16 + (lane & 15);
    #pragma unroll
    for (int g = 0; g < 2; g++) rB[g] = wn * 32 + g * 16 + (lane & 15);

    float acc[4][4][4] = {};
    float d1[8], d2[8]; int k1[8];
    #pragma unroll
    for (int i = 0; i < 8; i++) { d1[i] = 3.4e38f; d2[i] = 3.4e38f; k1[i] = 0; }

    uint4 pah[2], pal[2], pbh[2], pbl[2];
    // prologue g=0 (nt=0, kc=0)
    pah[0] = *(const uint4*)(g_a_hi + (size_t)(row0 + lr0) * DD + lc0 * 8);
    pah[1] = *(const uint4*)(g_a_hi + (size_t)(row0 + lr1) * DD + lc1 * 8);
    pal[0] = *(const uint4*)(g_a_lo + (size_t)(row0 + lr0) * DD + lc0 * 8);
    pal[1] = *(const uint4*)(g_a_lo + (size_t)(row0 + lr1) * DD + lc1 * 8);
    pbh[0] = *(const uint4*)(Bh + (size_t)lr0 * DD + lc0 * 8);
    pbh[1] = *(const uint4*)(Bh + (size_t)lr1 * DD + lc1 * 8);
    pbl[0] = *(const uint4*)(Bl + (size_t)lr0 * DD + lc0 * 8);
    pbl[1] = *(const uint4*)(Bl + (size_t)lr1 * DD + lc1 * 8);

    // 128 iterations: g = nt*16 + kc  (nt: 8 code tiles, kc: 16 K-chunks of 32)
    for (int g = 0; g < 128; ++g) {
        uint32_t bufo = (uint32_t)(g & 1) * BUF_B;
        char* s = smem + bufo;
        *(uint4*)(s + 0*TILE_B + so0) = pah[0]; *(uint4*)(s + 0*TILE_B + so1) = pah[1];
        *(uint4*)(s + 1*TILE_B + so0) = pal[0]; *(uint4*)(s + 1*TILE_B + so1) = pal[1];
        *(uint4*)(s + 2*TILE_B + so0) = pbh[0]; *(uint4*)(s + 2*TILE_B + so1) = pbh[1];
        *(uint4*)(s + 3*TILE_B + so0) = pbl[0]; *(uint4*)(s + 3*TILE_B + so1) = pbl[1];
        __syncthreads();

        if (g < 127) {
            int ng = g + 1;
            int nnt = ng >> 4, nkc = ng & 15;
            size_t a0 = (size_t)(row0 + lr0) * DD + nkc * 32 + lc0 * 8;
            size_t a1 = (size_t)(row0 + lr1) * DD + nkc * 32 + lc1 * 8;
            size_t b0 = (size_t)(nnt * 128 + lr0) * DD + nkc * 32 + lc0 * 8;
            size_t b1 = (size_t)(nnt * 128 + lr1) * DD + nkc * 32 + lc1 * 8;
            pah[0] = *(const uint4*)(g_a_hi + a0); pah[1] = *(const uint4*)(g_a_hi + a1);
            pal[0] = *(const uint4*)(g_a_lo + a0); pal[1] = *(const uint4*)(g_a_lo + a1);
            pbh[0] = *(const uint4*)(Bh + b0);     pbh[1] = *(const uint4*)(Bh + b1);
            pbl[0] = *(const uint4*)(Bl + b0);     pbl[1] = *(const uint4*)(Bl + b1);
        }

        uint32_t base = sb + bufo;
        #pragma unroll
        for (int ks = 0; ks < 2; ++ks) {
            int c16 = ks * 2 + hi16;
            uint32_t ah[4][4], al[4][4], bh[2][4], bl[2][4];
            #pragma unroll
            for (int mf = 0; mf < 4; mf++) {
                uint32_t off = (uint32_t)(rA[mf] * 64 + ((c16 ^ ((rA[mf] >> 1) & 3)) << 4));
                ldsm4(ah[mf], base + 0*TILE_B + off);
                ldsm4(al[mf], base + 1*TILE_B + off);
            }
            #pragma unroll
            for (int gp = 0; gp < 2; gp++) {
                uint32_t off = (uint32_t)(rB[gp] * 64 + ((c16 ^ ((rB[gp] >> 1) & 3)) << 4));
                ldsm4(bh[gp], base + 2*TILE_B + off);
                ldsm4(bl[gp], base + 3*TILE_B + off);
            }
            #pragma unroll
            for (int mf = 0; mf < 4; mf++)
                #pragma unroll
                for (int nf = 0; nf < 4; nf++) {
                    int gp = nf >> 1, od = nf & 1;
                    mma_bf16(acc[mf][nf], ah[mf], bh[gp][od], bh[gp][od + 2]);
                    mma_bf16(acc[mf][nf], ah[mf], bl[gp][od], bl[gp][od + 2]);
                    mma_bf16(acc[mf][nf], al[mf], bh[gp][od], bh[gp][od + 2]);
                }
        }

        if ((g & 15) == 15) {       // end of code tile: fold argmin, reset acc
            int nt = g >> 4;
            #pragma unroll
            for (int mf = 0; mf < 4; mf++)
                #pragma unroll
                for (int nf = 0; nf < 4; nf++) {
                    int c0 = nt * 128 + wn * 32 + nf * 8 + 2 * (lane & 3);
                    float n0 = __ldg(cn + c0), n1 = __ldg(cn + c0 + 1);
                    #pragma unroll
                    for (int sub = 0; sub < 2; sub++) {
                        int sl = mf * 2 + sub;
                        float e0 = n0 - 2.f * acc[mf][nf][sub * 2];
                        float e1 = n1 - 2.f * acc[mf][nf][sub * 2 + 1];
                        if (e0 < d1[sl]) { d2[sl] = d1[sl]; d1[sl] = e0; k1[sl] = c0; }
                        else if (e0 < d2[sl]) d2[sl] = e0;
                        if (e1 < d1[sl]) { d2[sl] = d1[sl]; d1[sl] = e1; k1[sl] = c0 + 1; }
                        else if (e1 < d2[sl]) d2[sl] = e1;
                        acc[mf][nf][sub * 2] = 0.f; acc[mf][nf][sub * 2 + 1] = 0.f;
                    }
                }
        }
        __syncthreads();
    }

    // cross-thread top-2 merge (alias tile smem)
    float* sd1 = (float*)smem;
    float* sd2 = (float*)(smem + 128 * 17 * 4);
    int*   sk1 = (int*)(smem + 2 * 128 * 17 * 4);
    int slot = wn * 4 + (lane & 3);
    #pragma unroll
    for (int sl = 0; sl < 8; sl++) {
        int mf = sl >> 1, sub = sl & 1;
        int r = wm * 64 + mf * 16 + sub * 8 + (lane >> 2);
        sd1[r * 17 + slot] = d1[sl];
        sd2[r * 17 + slot] = d2[sl];
        sk1[r * 17 + slot] = k1[sl];
    }
    __syncthreads();
    if (tid < 128) {
        float bd1 = 3.4e38f, bd2 = 3.4e38f; int bk = 0;
        #pragma unroll
        for (int j = 0; j < 16; j++) {
            float a1 = sd1[tid * 17 + j], a2 = sd2[tid * 17 + j];
            int ak = sk1[tid * 17 + j];
            if (a1 < bd1 || (a1 == bd1 && ak < bk)) {
                bd2 = fminf(bd1, a2); bd1 = a1; bk = ak;
            } else {
                bd2 = fminf(bd2, a1);
            }
        }
        int tok = row0 + tid;
        g_idx[stage * NTOK + tok] = bk;
        g_d1[tok] = bd1;
        g_d2[tok] = bd2;
    }
}

// ---------------- exact-fp32 fixup for near-tie tokens ----------------
__global__ void vq_fixup(const float* __restrict__ x, const float* __restrict__ cb, int stage) {
    int wg = (blockIdx.x * blockDim.x + threadIdx.x) >> 5;
    if (wg >= NTOK) return;
    int lane = threadIdx.x & 31;
    float gap = g_d2[wg] - g_d1[wg];
    if (gap > 0.05f) return;

    const float* r = (stage == 0) ? (x + (size_t)wg * DD) : (g_residual + (size_t)wg * DD);
    float rv[16];
    #pragma unroll
    for (int i = 0; i < 16; ++i) rv[i] = r[lane + 32 * i];
    const float* cbs = cb + (size_t)stage * KK_CB * DD;
    const float* cn = g_cnorm + stage * KK_CB;

    float bd = 3.4e38f; int bk = 0;
    for (int k = 0; k < KK_CB; ++k) {
        const float* c = cbs + (size_t)k * DD;
        float s = 0.f;
        #pragma unroll
        for (int i = 0; i < 16; ++i) s += rv[i] * c[lane + 32 * i];
        #pragma unroll
        for (int o = 16; o > 0; o >>= 1) s += __shfl_xor_sync(0xffffffffu, s, o);
        float d = cn[k] - 2.0f * s;
        if (d < bd) { bd = d; bk = k; }
    }
    if (lane == 0) g_idx[stage * NTOK + wg] = bk;
}

// ---------------- residual update: fp32 + bf16 splits + loss ----------------
__global__ void vq_update_kernel(const float* __restrict__ x,
                                 const float* __restrict__ cb_stage,
                                 int stage) {
    __shared__ float sred[256];
    const float4* src = (const float4*)((stage == 0) ? x : g_residual);
    float4* res = (float4*)g_residual;
    const float4* cb4 = (const float4*)cb_stage;
    const int* idx = g_idx + stage * NTOK;

    float lsum = 0.f;
    int n4 = NELEM / 4;
    for (int e = blockIdx.x * blockDim.x + threadIdx.x; e < n4; e += gridDim.x * blockDim.x) {
        int tok = e >> 7;
        int d4  = e & 127;
        int k   = __ldg(idx + tok);
        float4 r = src[e];
        float4 q = cb4[(size_t)k * 128 + d4];
        float nx = r.x - q.x, ny = r.y - q.y, nz = r.z - q.z, nw = r.w - q.w;
        lsum += nx * nx + ny * ny + nz * nz + nw * nw;
        res[e] = make_float4(nx, ny, nz, nw);
        if (stage < QQ - 1) {
            int b = e * 4;
            split1(nx, g_a_hi[b+0], g_a_lo[b+0]);
            split1(ny, g_a_hi[b+1], g_a_lo[b+1]);
            split1(nz, g_a_hi[b+2], g_a_lo[b+2]);
            split1(nw, g_a_hi[b+3], g_a_lo[b+3]);
        }
    }
    sred[threadIdx.x] = lsum;
    __syncthreads();
    for (int o = 128; o > 0; o >>= 1) {
        if (threadIdx.x < o) sred[threadIdx.x] += sred[threadIdx.x + o];
        __syncthreads();
    }
    if (threadIdx.x == 0) atomicAdd(&g_loss, (double)sred[0]);
}

// ---------------- quantized_out = x - residual ; emit splits ----------------
__global__ void finish_quant_kernel(const float* __restrict__ x, float* __restrict__ quant) {
    int n4 = NELEM / 4;
    const float4* x4 = (const float4*)x;
    const float4* r4 = (const float4*)g_residual;
    float4* q4 = (float4*)quant;
    for (int e = blockIdx.x * blockDim.x + threadIdx.x; e < n4; e += gridDim.x * blockDim.x) {
        float4 a = x4[e], b = r4[e];
        float4 q = make_float4(a.x - b.x, a.y - b.y, a.z - b.z, a.w - b.w);
        q4[e] = q;
        int i = e * 4;
        split1(q.x, g_q_hi[i+0], g_q_lo[i+0]);
        split1(q.y, g_q_hi[i+1], g_q_lo[i+1]);
        split1(q.z, g_q_hi[i+2], g_q_lo[i+2]);
        split1(q.w, g_q_hi[i+3], g_q_lo[i+3]);
    }
}

// ---------------- conv1d (stride2, SAME) + GELU via mma.sync, swizzled ----------------
__global__ __launch_bounds__(256)
void conv_mma(float* __restrict__ y) {
    extern __shared__ char smem[];
    uint32_t sb = smem_u32(smem);
    int tid = threadIdx.x, lane = tid & 31, w = tid >> 5;
    int wm = w & 1, wn = w >> 1;
    int row0 = blockIdx.x * 128;
    int col0 = blockIdx.y * 128;

    int lr0 = tid >> 2,        lc0 = tid & 3;
    int lr1 = (tid + 256) >> 2, lc1 = (tid + 256) & 3;
    uint32_t so0 = swz(lr0, lc0), so1 = swz(lr1, lc1);

    // A row decomposition (fixed per thread)
    int ar0 = row0 + lr0, ab0 = ar0 >> 11, at0 = ar0 & (TOUT - 1);
    int ar1 = row0 + lr1, ab1 = ar1 >> 11, at1 = ar1 & (TOUT - 1);

    int hi16 = (lane >> 4) & 1;
    int rA[4], rB[2];
    #pragma unroll
    for (int mf = 0; mf < 4; mf++) rA[mf] = wm * 64 + mf * 16 + (lane & 15);
    #pragma unroll
    for (int g = 0; g < 2; g++) rB[g] = wn * 32 + g * 16 + (lane & 15);

    float acc[4][4][4] = {};

    uint4 pah[2], pal[2], pbh[2], pbl[2];
    // prologue g=0: kk=0, cin0=0, tin = 2*to - 1
    {
        int t0 = 2 * at0 - 1, t1 = 2 * at1 - 1;
        pah[0] = pah[1] = pal[0] = pal[1] = make_uint4(0,0,0,0);
        if ((unsigned)t0 < (unsigned)TT) {
            size_t a = ((size_t)ab0 * TT + t0) * DD + lc0 * 8;
            pah[0] = *(const uint4*)(g_q_hi + a);
            pal[0] = *(const uint4*)(g_q_lo + a);
        }
        if ((unsigned)t1 < (unsigned)TT) {
            size_t a = ((size_t)ab1 * TT + t1) * DD + lc1 * 8;
            pah[1] = *(const uint4*)(g_q_hi + a);
            pal[1] = *(const uint4*)(g_q_lo + a);
        }
        size_t b0 = (size_t)(col0 + lr0) * KCONV + lc0 * 8;
        size_t b1 = (size_t)(col0 + lr1) * KCONV + lc1 * 8;
        pbh[0] = *(const uint4*)(g_wt_hi + b0); pbh[1] = *(const uint4*)(g_wt_hi + b1);
        pbl[0] = *(const uint4*)(g_wt_lo + b0); pbl[1] = *(const uint4*)(g_wt_lo + b1);
    }

    // 80 chunks: g = kk*16 + kc  (kk: 5 taps, kc: 16 chunks of 32 over 512 channels)
    for (int g = 0; g < 80; ++g) {
        uint32_t bufo = (uint32_t)(g & 1) * BUF_B;
        char* s = smem + bufo;
        *(uint4*)(s + 0*TILE_B + so0) = pah[0]; *(uint4*)(s + 0*TILE_B + so1) = pah[1];
        *(uint4*)(s + 1*TILE_B + so0) = pal[0]; *(uint4*)(s + 1*TILE_B + so1) = pal[1];
        *(uint4*)(s + 2*TILE_B + so0) = pbh[0]; *(uint4*)(s + 2*TILE_B + so1) = pbh[1];
        *(uint4*)(s + 3*TILE_B + so0) = pbl[0]; *(uint4*)(s + 3*TILE_B + so1) = pbl[1];
        __syncthreads();

        if (g < 79) {
            int ng = g + 1;
            int kk = ng >> 4, cin0 = (ng & 15) * 32;
            int t0 = 2 * at0 + kk - 1, t1 = 2 * at1 + kk - 1;
            pah[0] = pah[1] = pal[0] = pal[1] = make_uint4(0,0,0,0);
            if ((unsigned)t0 < (unsigned)TT) {
                size_t a = ((size_t)ab0 * TT + t0) * DD + cin0 + lc0 * 8;
                pah[0] = *(const uint4*)(g_q_hi + a);
                pal[0] = *(const uint4*)(g_q_lo + a);
            }
            if ((unsigned)t1 < (unsigned)TT) {
                size_t a = ((size_t)ab1 * TT + t1) * DD + cin0 + lc1 * 8;
                pah[1] = *(const uint4*)(g_q_hi + a);
                pal[1] = *(const uint4*)(g_q_lo + a);
            }
            int koff = kk * DD + cin0;
            size_t b0 = (size_t)(col0 + lr0) * KCONV + koff + lc0 * 8;
            size_t b1 = (size_t)(col0 + lr1) * KCONV + koff + lc1 * 8;
            pbh[0] = *(const uint4*)(g_wt_hi + b0); pbh[1] = *(const uint4*)(g_wt_hi + b1);
            pbl[0] = *(const uint4*)(g_wt_lo + b0); pbl[1] = *(const uint4*)(g_wt_lo + b1);
        }

        uint32_t base = sb + bufo;
        #pragma unroll
        for (int ks = 0; ks < 2; ++ks) {
            int c16 = ks * 2 + hi16;
            uint32_t ah[4][4], al[4][4], bh[2][4], bl[2][4];
            #pragma unroll
            for (int mf = 0; mf < 4; mf++) {
                uint32_t off = (uint32_t)(rA[mf] * 64 + ((c16 ^ ((rA[mf] >> 1) & 3)) << 4));
                ldsm4(ah[mf], base + 0*TILE_B + off);
                ldsm4(al[mf], base + 1*TILE_B + off);
            }
            #pragma unroll
            for (int gp = 0; gp < 2; gp++) {
                uint32_t off = (uint32_t)(rB[gp] * 64 + ((c16 ^ ((rB[gp] >> 1) & 3)) << 4));
                ldsm4(bh[gp], base + 2*TILE_B + off);
                ldsm4(bl[gp], base + 3*TILE_B + off);
            }
            #pragma unroll
            for (int mf = 0; mf < 4; mf++)
                #pragma unroll
                for (int nf = 0; nf < 4; nf++) {
                    int gp = nf >> 1, od = nf & 1;
                    mma_bf16(acc[mf][nf], ah[mf], bh[gp][od], bh[gp][od + 2]);
                    mma_bf16(acc[mf][nf], ah[mf], bl[gp][od], bl[gp][od + 2]);
                    mma_bf16(acc[mf][nf], al[mf], bh[gp][od], bh[gp][od + 2]);
                }
        }
        __syncthreads();
    }

    // epilogue: GELU + store
    #pragma unroll
    for (int mf = 0; mf < 4; mf++) {
        int r0 = row0 + wm * 64 + mf * 16 + (lane >> 2);
        #pragma unroll
        for (int nf = 0; nf < 4; nf++) {
            int c0 = col0 + wn * 32 + nf * 8 + 2 * (lane & 3);
            #pragma unroll
            for (int q = 0; q < 4; q++) {
                int row = r0 + (q >> 1) * 8;
                int col = c0 + (q & 1);
                float v = acc[mf][nf][q];
                float gl = 0.5f * v * (1.0f + erff(v * 0.70710678118654752f));
                y[(size_t)row * DD + col] = gl;
            }
        }
    }
}

// ---------------- indices (as float) + loss ----------------
__global__ void finalize_kernel(float* __restrict__ out) {
    int i = blockIdx.x * blockDim.x + threadIdx.x;
    if (i < IDX_SZ) out[Y_SZ + QO_SZ + i] = (float)g_idx[i];
    if (i == 0)     out[LOSS_OFF] = (float)(0.25 * g_loss / (double)NELEM);
}

// ---------------- launch ----------------
extern "C" void kernel_launch(void* const* d_in, const int* in_sizes, int n_in,
                              void* d_out, int out_size) {
    const float* x  = (const float*)d_in[0];
    const float* cb = (const float*)d_in[1];
    const float* w  = (const float*)d_in[2];
    float* out   = (float*)d_out;
    float* y     = out;
    float* quant = out + Y_SZ;

    cudaFuncSetAttribute(vq_mma, cudaFuncAttributeMaxDynamicSharedMemorySize, SMEM_DYN);
    cudaFuncSetAttribute(conv_mma, cudaFuncAttributeMaxDynamicSharedMemorySize, SMEM_DYN);

    cnorm_kernel<<<(QQ * KK_CB * 32 + 255) / 256, 256>>>(cb);
    split_x_kernel<<<2048, 256>>>(x);
    split_cb_kernel<<<2048, 256>>>(cb);
    transpose_w_kernel<<<2048, 256>>>(w);

    for (int s = 0; s < QQ; ++s) {
        vq_mma<<<NTOK / 128, 256, SMEM_DYN>>>(s);
        vq_fixup<<<NTOK / 8, 256>>>(x, cb, s);
        vq_update_kernel<<<2048, 256>>>(x, cb + (size_t)s * KK_CB * DD, s);
    }
    finish_quant_kernel<<<4096, 256>>>(x, quant);
    conv_mma<<<dim3(BB * TOUT / 128, DD / 128), 256, SMEM_DYN>>>(y);
    finalize_kernel<<<(IDX_SZ + 255) / 256, 256>>>(out);
}

// round 7
// speedup vs baseline: 2.3462x; 2.3462x over previous
#include <cuda_runtime.h>
#include <cuda_fp16.h>
#include <math.h>
#include <stdint.h>

// ---------------- problem constants ----------------
#define BB      8
#define TT      4096
#define DD      512
#define QQ      4
#define KK_CB   1024
#define KER     5
#define TOUT    2048
#define NTOK    32768
#define NELEM   (NTOK * DD)              // 16777216
#define Y_SZ    (BB * TOUT * DD)         // 8388608
#define QO_SZ   NELEM
#define IDX_SZ  (QQ * NTOK)
#define LOSS_OFF (Y_SZ + QO_SZ + IDX_SZ)
#define MARGIN  3.0f

// ---------------- persistent scratch ----------------
__device__ float  g_residual[NELEM];            // exact fp32 residual
__device__ __half g_r16[NELEM];                 // fp16 mirror for screening
__device__ __half g_cb16[QQ * KK_CB * DD];      // fp16 codebooks
__device__ float  g_dist[(size_t)NTOK * KK_CB]; // 128 MB approx distances
__device__ float  g_cnorm[QQ * KK_CB];
__device__ int    g_idx[QQ * NTOK];
__device__ double g_loss;

// ---------------- prep kernels ----------------
__global__ void cnorm_kernel(const float* __restrict__ cb) {
    if (blockIdx.x == 0 && threadIdx.x == 0) g_loss = 0.0;
    int w    = (blockIdx.x * blockDim.x + threadIdx.x) >> 5;
    int lane = threadIdx.x & 31;
    if (w >= QQ * KK_CB) return;
    const float* c = cb + (size_t)w * DD;
    float s = 0.f;
    #pragma unroll
    for (int d = lane; d < DD; d += 32) { float v = c[d]; s += v * v; }
    #pragma unroll
    for (int o = 16; o > 0; o >>= 1) s += __shfl_down_sync(0xffffffffu, s, o);
    if (lane == 0) g_cnorm[w] = s;
}
__global__ void tohalf_x(const float* __restrict__ x) {
    for (int e = blockIdx.x * blockDim.x + threadIdx.x; e < NELEM; e += gridDim.x * blockDim.x)
        g_r16[e] = __float2half(x[e]);
}
__global__ void tohalf_cb(const float* __restrict__ cb) {
    int n = QQ * KK_CB * DD;
    for (int e = blockIdx.x * blockDim.x + threadIdx.x; e < n; e += gridDim.x * blockDim.x)
        g_cb16[e] = __float2half(cb[e]);
}

// ---------------- fp16 screening GEMM: approx distances for all codes ----------------
// dist(token,k) ~= ||c_k||^2 - 2 * <r, c_k>_fp16
// Tile 128 tokens x 128 codes, K-chunk 32 dims (16 half2 rows), 8x8 half2 microtile.
__global__ __launch_bounds__(256, 2)
void screen_kernel(int stage) {
    __shared__ __align__(16) uint32_t As2[16][132];
    __shared__ __align__(16) uint32_t Bs2[16][132];

    int t  = threadIdx.x;
    int tx = t & 15, ty = t >> 4;
    int row0 = blockIdx.x * 128;

    const __half* __restrict__ Ab = g_r16;
    const __half* __restrict__ Bb = g_cb16 + (size_t)stage * KK_CB * DD;
    const float*  __restrict__ cn = g_cnorm + stage * KK_CB;

    half2 acc[8][8];
    #pragma unroll
    for (int i = 0; i < 8; i++)
        #pragma unroll
        for (int j = 0; j < 8; j++) acc[i][j] = __float2half2_rn(0.f);

    int lr0 = t >> 2,         lc0 = t & 3;
    int lr1 = (t + 256) >> 2, lc1 = (t + 256) & 3;

    uint4 pa0, pa1, pb0, pb1;
    // prologue: chunk 0 (nt=0, kc=0)
    pa0 = *(const uint4*)(Ab + (size_t)(row0 + lr0) * DD + lc0 * 8);
    pa1 = *(const uint4*)(Ab + (size_t)(row0 + lr1) * DD + lc1 * 8);
    pb0 = *(const uint4*)(Bb + (size_t)lr0 * DD + lc0 * 8);
    pb1 = *(const uint4*)(Bb + (size_t)lr1 * DD + lc1 * 8);

    // 128 iterations: g = nt*16 + kc   (8 code tiles x 16 chunks of 32 dims)
    for (int g = 0; g < 128; ++g) {
        {   // scatter prefetched uint4 (8 halves = 4 half2 rows) into smem
            const uint32_t* w0 = (const uint32_t*)&pa0;
            const uint32_t* w1 = (const uint32_t*)&pa1;
            const uint32_t* v0 = (const uint32_t*)&pb0;
            const uint32_t* v1 = (const uint32_t*)&pb1;
            #pragma unroll
            for (int j = 0; j < 4; j++) {
                As2[4*lc0 + j][lr0] = w0[j];
                As2[4*lc1 + j][lr1] = w1[j];
                Bs2[4*lc0 + j][lr0] = v0[j];
                Bs2[4*lc1 + j][lr1] = v1[j];
            }
        }
        __syncthreads();

        if (g < 127) {
            int ng = g + 1;
            int nt = ng >> 4, kc = ng & 15;
            size_t a0 = (size_t)(row0 + lr0) * DD + kc * 32 + lc0 * 8;
            size_t a1 = (size_t)(row0 + lr1) * DD + kc * 32 + lc1 * 8;
            size_t b0 = (size_t)(nt * 128 + lr0) * DD + kc * 32 + lc0 * 8;
            size_t b1 = (size_t)(nt * 128 + lr1) * DD + kc * 32 + lc1 * 8;
            pa0 = *(const uint4*)(Ab + a0);
            pa1 = *(const uint4*)(Ab + a1);
            pb0 = *(const uint4*)(Bb + b0);
            pb1 = *(const uint4*)(Bb + b1);
        }

        #pragma unroll
        for (int kp = 0; kp < 16; ++kp) {
            half2 a2[8], b2[8];
            uint4 ua0 = *(const uint4*)&As2[kp][ty * 8];
            uint4 ua1 = *(const uint4*)&As2[kp][ty * 8 + 4];
            uint4 ub0 = *(const uint4*)&Bs2[kp][tx * 8];
            uint4 ub1 = *(const uint4*)&Bs2[kp][tx * 8 + 4];
            const half2* ap0 = (const half2*)&ua0; const half2* ap1 = (const half2*)&ua1;
            const half2* bp0 = (const half2*)&ub0; const half2* bp1 = (const half2*)&ub1;
            #pragma unroll
            for (int i = 0; i < 4; i++) { a2[i] = ap0[i]; a2[i+4] = ap1[i]; b2[i] = bp0[i]; b2[i+4] = bp1[i]; }
            #pragma unroll
            for (int i = 0; i < 8; i++)
                #pragma unroll
                for (int j = 0; j < 8; j++)
                    acc[i][j] = __hfma2(a2[i], b2[j], acc[i][j]);
        }

        if ((g & 15) == 15) {   // end of code tile: convert + store distances, reset acc
            int nt = g >> 4;
            int col0 = nt * 128 + tx * 8;
            #pragma unroll
            for (int i = 0; i < 8; i++) {
                int row = row0 + ty * 8 + i;
                float dd[8];
                #pragma unroll
                for (int j = 0; j < 8; j++) {
                    half2 s = acc[i][j];
                    float dot = __low2float(s) + __high2float(s);
                    dd[j] = __ldg(cn + col0 + j) - 2.0f * dot;
                    acc[i][j] = __float2half2_rn(0.f);
                }
                float* dp = g_dist + (size_t)row * KK_CB + col0;
                *(float4*)(dp)     = make_float4(dd[0], dd[1], dd[2], dd[3]);
                *(float4*)(dp + 4) = make_float4(dd[4], dd[5], dd[6], dd[7]);
            }
        }
        __syncthreads();
    }
}

// ---------------- rescue: exact fp32 rescore of codes within MARGIN of approx min ----------------
__global__ void rescue_kernel(const float* __restrict__ x,
                              const float* __restrict__ cb, int stage) {
    int tok  = blockIdx.x * 8 + (threadIdx.x >> 5);
    int lane = threadIdx.x & 31;
    if (tok >= NTOK) return;

    const float* __restrict__ dist = g_dist + (size_t)tok * KK_CB;
    float m = 3.4e38f;
    for (int j = lane; j < KK_CB; j += 32) m = fminf(m, dist[j]);
    #pragma unroll
    for (int o = 16; o > 0; o >>= 1) m = fminf(m, __shfl_xor_sync(0xffffffffu, m, o));
    float thr = m + MARGIN;

    const float* r = (stage == 0) ? (x + (size_t)tok * DD) : (g_residual + (size_t)tok * DD);
    float rv[16];
    #pragma unroll
    for (int i = 0; i < 16; ++i) rv[i] = r[lane + 32 * i];

    const float* cbs = cb + (size_t)stage * KK_CB * DD;
    const float* cnp = g_cnorm + stage * KK_CB;

    float bd = 3.4e38f; int bk = 0;
    for (int j0 = 0; j0 < KK_CB; j0 += 32) {
        float dv = dist[j0 + lane];
        unsigned mask = __ballot_sync(0xffffffffu, dv <= thr);
        while (mask) {
            int j = j0 + __ffs(mask) - 1;
            mask &= mask - 1;
            const float* c = cbs + (size_t)j * DD;
            float s = 0.f;
            #pragma unroll
            for (int i = 0; i < 16; ++i) s += rv[i] * c[lane + 32 * i];
            #pragma unroll
            for (int o = 16; o > 0; o >>= 1) s += __shfl_xor_sync(0xffffffffu, s, o);
            float de = __ldg(cnp + j) - 2.0f * s;
            if (de < bd) { bd = de; bk = j; }   // ascending j => first-min tie-break
        }
    }
    if (lane == 0) g_idx[stage * NTOK + tok] = bk;
}

// ---------------- residual update (exact fp32) + fp16 mirror + loss + stage-3 quant ----------------
__global__ void update_kernel(const float* __restrict__ x,
                              const float* __restrict__ cb_stage,
                              float* __restrict__ quant, int stage) {
    __shared__ float sred[256];
    const float4* src = (const float4*)((stage == 0) ? x : g_residual);
    float4* res = (float4*)g_residual;
    const float4* cb4 = (const float4*)cb_stage;
    const float4* x4  = (const float4*)x;
    float4* q4 = (float4*)quant;
    const int* idx = g_idx + stage * NTOK;

    float lsum = 0.f;
    int n4 = NELEM / 4;
    for (int e = blockIdx.x * blockDim.x + threadIdx.x; e < n4; e += gridDim.x * blockDim.x) {
        int tok = e >> 7;
        int d4  = e & 127;
        int k   = __ldg(idx + tok);
        float4 r = src[e];
        float4 q = cb4[(size_t)k * 128 + d4];
        float nx = r.x - q.x, ny = r.y - q.y, nz = r.z - q.z, nw = r.w - q.w;
        lsum += nx * nx + ny * ny + nz * nz + nw * nw;
        res[e] = make_float4(nx, ny, nz, nw);
        if (stage < QQ - 1) {
            *(half2*)&g_r16[e * 4]     = __floats2half2_rn(nx, ny);
            *(half2*)&g_r16[e * 4 + 2] = __floats2half2_rn(nz, nw);
        } else {
            float4 xv = x4[e];
            q4[e] = make_float4(xv.x - nx, xv.y - ny, xv.z - nz, xv.w - nw);
        }
    }
    sred[threadIdx.x] = lsum;
    __syncthreads();
    for (int o = 128; o > 0; o >>= 1) {
        if (threadIdx.x < o) sred[threadIdx.x] += sred[threadIdx.x + o];
        __syncthreads();
    }
    if (threadIdx.x == 0) atomicAdd(&g_loss, (double)sred[0]);
}

// ---------------- conv1d (stride 2, SAME, pad_lo=1) + exact GELU (proven R4 fp32) ----------------
__global__ __launch_bounds__(256)
void conv_gelu_kernel(const float* __restrict__ quant,
                      const float* __restrict__ W,
                      float* __restrict__ y) {
    __shared__ __align__(16) float As[16][132];
    __shared__ __align__(16) float Bs[16][132];

    int t  = threadIdx.x;
    int tx = t & 15, ty = t >> 4;
    int mrow0 = blockIdx.x * 128;
    int ncol0 = blockIdx.y * 128;

    float acc[8][8];
    #pragma unroll
    for (int i = 0; i < 8; i++)
        #pragma unroll
        for (int j = 0; j < 8; j++) acc[i][j] = 0.f;

    for (int kk = 0; kk < KER; ++kk) {
        const float* Wk = W + (size_t)kk * DD * DD;
        for (int c0 = 0; c0 < DD; c0 += 16) {
            #pragma unroll
            for (int i = 0; i < 2; i++) {
                int idx = t + 256 * i;
                int r = idx >> 2, c = idx & 3;
                int row = mrow0 + r;
                int b   = row >> 11;
                int to  = row & (TOUT - 1);
                int tin = 2 * to + kk - 1;
                float4 va = make_float4(0.f, 0.f, 0.f, 0.f);
                if ((unsigned)tin < (unsigned)TT)
                    va = *(const float4*)(quant + ((size_t)b * TT + tin) * DD + c0 + 4 * c);
                As[4*c+0][r] = va.x; As[4*c+1][r] = va.y;
                As[4*c+2][r] = va.z; As[4*c+3][r] = va.w;
                int ci = idx >> 5, cq = idx & 31;
                float4 vb = *(const float4*)(Wk + (size_t)(c0 + ci) * DD + ncol0 + cq * 4);
                *(float4*)&Bs[ci][cq * 4] = vb;
            }
            __syncthreads();
            #pragma unroll
            for (int kki = 0; kki < 16; ++kki) {
                float a[8], b[8];
                *(float4*)(a)     = *(const float4*)&As[kki][ty * 8];
                *(float4*)(a + 4) = *(const float4*)&As[kki][ty * 8 + 4];
                *(float4*)(b)     = *(const float4*)&Bs[kki][tx * 8];
                *(float4*)(b + 4) = *(const float4*)&Bs[kki][tx * 8 + 4];
                #pragma unroll
                for (int i = 0; i < 8; i++)
                    #pragma unroll
                    for (int j = 0; j < 8; j++) acc[i][j] += a[i] * b[j];
            }
            __syncthreads();
        }
    }
    #pragma unroll
    for (int i = 0; i < 8; i++) {
        int row = mrow0 + ty * 8 + i;
        #pragma unroll
        for (int j = 0; j < 8; j++) {
            int co = ncol0 + tx * 8 + j;
            float v = acc[i][j];
            float g = 0.5f * v * (1.0f + erff(v * 0.70710678118654752f));
            y[(size_t)row * DD + co] = g;
        }
    }
}

// ---------------- indices (as float) + loss ----------------
__global__ void finalize_kernel(float* __restrict__ out) {
    int i = blockIdx.x * blockDim.x + threadIdx.x;
    if (i < IDX_SZ) out[Y_SZ + QO_SZ + i] = (float)g_idx[i];
    if (i == 0)     out[LOSS_OFF] = (float)(0.25 * g_loss / (double)NELEM);
}

// ---------------- launch ----------------
extern "C" void kernel_launch(void* const* d_in, const int* in_sizes, int n_in,
                              void* d_out, int out_size) {
    const float* x  = (const float*)d_in[0];
    const float* cb = (const float*)d_in[1];
    const float* w  = (const float*)d_in[2];
    float* out   = (float*)d_out;
    float* y     = out;
    float* quant = out + Y_SZ;

    cnorm_kernel<<<(QQ * KK_CB * 32 + 255) / 256, 256>>>(cb);
    tohalf_x<<<2048, 256>>>(x);
    tohalf_cb<<<1024, 256>>>(cb);

    for (int s = 0; s < QQ; ++s) {
        screen_kernel<<<NTOK / 128, 256>>>(s);
        rescue_kernel<<<NTOK / 8, 256>>>(x, cb, s);
        update_kernel<<<2048, 256>>>(x, cb + (size_t)s * KK_CB * DD, quant, s);
    }
    conv_gelu_kernel<<<dim3(BB * TOUT / 128, DD / 128), 256>>>(quant, w, y);
    finalize_kernel<<<(IDX_SZ + 255) / 256, 256>>>(out);
}

// round 8
// speedup vs baseline: 2.8172x; 1.2007x over previous
#include <cuda_runtime.h>
#include <cuda_fp16.h>
#include <math.h>
#include <stdint.h>

// ---------------- problem constants ----------------
#define BB      8
#define TT      4096
#define DD      512
#define QQ      4
#define KK_CB   1024
#define KER     5
#define TOUT    2048
#define NTOK    32768
#define NELEM   (NTOK * DD)              // 16777216
#define Y_SZ    (BB * TOUT * DD)         // 8388608
#define QO_SZ   NELEM
#define IDX_SZ  (QQ * NTOK)
#define LOSS_OFF (Y_SZ + QO_SZ + IDX_SZ)
#define MARGIN  3.0f
#define MTILE   112
#define NGRID   ((NTOK + MTILE - 1) / MTILE)   // 293

// ---------------- persistent scratch ----------------
__device__ float  g_residual[NELEM];            // exact fp32 residual
__device__ __half g_r16[NELEM];                 // fp16 mirror for screening
__device__ __half g_cb16[QQ * KK_CB * DD];      // fp16 codebooks
__device__ float  g_dist[(size_t)NTOK * KK_CB]; // approx distances (128 MB)
__device__ float  g_table[(size_t)KER * 4096 * DD]; // U[kk][s*1024+code][dout] (42 MB)
__device__ float  g_cnorm[QQ * KK_CB];
__device__ float  g_d1[NTOK];
__device__ int    g_idx[QQ * NTOK];
__device__ double g_loss;

// ---------------- prep kernels ----------------
__global__ void cnorm_kernel(const float* __restrict__ cb) {
    if (blockIdx.x == 0 && threadIdx.x == 0) g_loss = 0.0;
    int w    = (blockIdx.x * blockDim.x + threadIdx.x) >> 5;
    int lane = threadIdx.x & 31;
    if (w >= QQ * KK_CB) return;
    const float* c = cb + (size_t)w * DD;
    float s = 0.f;
    #pragma unroll
    for (int d = lane; d < DD; d += 32) { float v = c[d]; s += v * v; }
    #pragma unroll
    for (int o = 16; o > 0; o >>= 1) s += __shfl_down_sync(0xffffffffu, s, o);
    if (lane == 0) g_cnorm[w] = s;
}
__global__ void tohalf_x(const float* __restrict__ x) {
    for (int e = blockIdx.x * blockDim.x + threadIdx.x; e < NELEM; e += gridDim.x * blockDim.x)
        g_r16[e] = __float2half(x[e]);
}
__global__ void tohalf_cb(const float* __restrict__ cb) {
    int n = QQ * KK_CB * DD;
    for (int e = blockIdx.x * blockDim.x + threadIdx.x; e < n; e += gridDim.x * blockDim.x)
        g_cb16[e] = __float2half(cb[e]);
}

// ---------------- conv table GEMM: U[kk][code][dout] = sum_din cb[code][din]*W[kk][din][dout] ----------------
__global__ __launch_bounds__(256)
void tableg_kernel(const float* __restrict__ cb,
                   const float* __restrict__ W) {
    __shared__ __align__(16) float As[16][132];
    __shared__ __align__(16) float Bs[16][132];

    int t  = threadIdx.x;
    int tx = t & 15, ty = t >> 4;
    int crow0 = blockIdx.x * 128;          // code rows (0..4095)
    int ncol0 = blockIdx.y * 128;          // dout
    int kk    = blockIdx.z;                // tap

    const float* Wk = W + (size_t)kk * DD * DD;

    float acc[8][8];
    #pragma unroll
    for (int i = 0; i < 8; i++)
        #pragma unroll
        for (int j = 0; j < 8; j++) acc[i][j] = 0.f;

    for (int c0 = 0; c0 < DD; c0 += 16) {
        #pragma unroll
        for (int i = 0; i < 2; i++) {
            int idx = t + 256 * i;
            int r = idx >> 2, c = idx & 3;
            float4 va = *(const float4*)(cb + (size_t)(crow0 + r) * DD + c0 + 4 * c);
            As[4*c+0][r] = va.x; As[4*c+1][r] = va.y;
            As[4*c+2][r] = va.z; As[4*c+3][r] = va.w;
            int ci = idx >> 5, cq = idx & 31;
            float4 vb = *(const float4*)(Wk + (size_t)(c0 + ci) * DD + ncol0 + cq * 4);
            *(float4*)&Bs[ci][cq * 4] = vb;
        }
        __syncthreads();
        #pragma unroll
        for (int kki = 0; kki < 16; ++kki) {
            float a[8], b[8];
            *(float4*)(a)     = *(const float4*)&As[kki][ty * 8];
            *(float4*)(a + 4) = *(const float4*)&As[kki][ty * 8 + 4];
            *(float4*)(b)     = *(const float4*)&Bs[kki][tx * 8];
            *(float4*)(b + 4) = *(const float4*)&Bs[kki][tx * 8 + 4];
            #pragma unroll
            for (int i = 0; i < 8; i++)
                #pragma unroll
                for (int j = 0; j < 8; j++) acc[i][j] += a[i] * b[j];
        }
        __syncthreads();
    }
    #pragma unroll
    for (int i = 0; i < 8; i++) {
        int row = crow0 + ty * 8 + i;
        float* dst = g_table + ((size_t)kk * 4096 + row) * DD + ncol0 + tx * 8;
        *(float4*)(dst)     = make_float4(acc[i][0], acc[i][1], acc[i][2], acc[i][3]);
        *(float4*)(dst + 4) = make_float4(acc[i][4], acc[i][5], acc[i][6], acc[i][7]);
    }
}

// ---------------- fp16 screening GEMM (M-tile 112 for wave balance) ----------------
__global__ __launch_bounds__(256, 2)
void screen_kernel(int stage) {
    __shared__ union {
        struct { __align__(16) uint32_t A[16][116]; __align__(16) uint32_t B[16][132]; } tb;
        struct { float d[MTILE][17]; } red;
    } sm;

    int t  = threadIdx.x;
    int tx = t & 15, ty = t >> 4;          // ty 0..15; compute active ty<14
    int row0 = blockIdx.x * MTILE;
    bool act = (ty < 14);

    const __half* __restrict__ Ab = g_r16;
    const __half* __restrict__ Bb = g_cb16 + (size_t)stage * KK_CB * DD;
    const float*  __restrict__ cn = g_cnorm + stage * KK_CB;

    half2 acc[8][8];
    #pragma unroll
    for (int i = 0; i < 8; i++)
        #pragma unroll
        for (int j = 0; j < 8; j++) acc[i][j] = __float2half2_rn(0.f);

    float d1[8];
    #pragma unroll
    for (int i = 0; i < 8; i++) d1[i] = 3.4e38f;

    // loader mapping: A has 448 uint4 (112 rows x 4), B has 512 (128 rows x 4)
    int ar0 = t >> 2,           ac0 = t & 3;
    int ar1 = (t + 256) >> 2,   ac1 = (t + 256) & 3;  // ar1 may be >=112 -> masked
    bool a1v = (ar1 < MTILE);
    int ar1c = a1v ? ar1 : 0;
    int br0 = ar0, bc0 = ac0;
    int br1 = ar1 & 127, bc1 = ac1;
    int tokA0 = min(row0 + ar0, NTOK - 1);
    int tokA1 = min(row0 + ar1c, NTOK - 1);

    uint4 pa0, pa1, pb0, pb1;
    pa0 = *(const uint4*)(Ab + (size_t)tokA0 * DD + ac0 * 8);
    pa1 = *(const uint4*)(Ab + (size_t)tokA1 * DD + ac1 * 8);
    pb0 = *(const uint4*)(Bb + (size_t)br0 * DD + bc0 * 8);
    pb1 = *(const uint4*)(Bb + (size_t)br1 * DD + bc1 * 8);

    for (int g = 0; g < 128; ++g) {
        {
            const uint32_t* w0 = (const uint32_t*)&pa0;
            const uint32_t* w1 = (const uint32_t*)&pa1;
            const uint32_t* v0 = (const uint32_t*)&pb0;
            const uint32_t* v1 = (const uint32_t*)&pb1;
            #pragma unroll
            for (int j = 0; j < 4; j++) {
                sm.tb.A[4*ac0 + j][ar0] = w0[j];
                if (a1v) sm.tb.A[4*ac1 + j][ar1] = w1[j];
                sm.tb.B[4*bc0 + j][br0] = v0[j];
                sm.tb.B[4*bc1 + j][br1] = v1[j];
            }
        }
        __syncthreads();

        if (g < 127) {
            int ng = g + 1;
            int nt = ng >> 4, kc = ng & 15;
            pa0 = *(const uint4*)(Ab + (size_t)tokA0 * DD + kc * 32 + ac0 * 8);
            pa1 = *(const uint4*)(Ab + (size_t)tokA1 * DD + kc * 32 + ac1 * 8);
            pb0 = *(const uint4*)(Bb + (size_t)(nt * 128 + br0) * DD + kc * 32 + bc0 * 8);
            pb1 = *(const uint4*)(Bb + (size_t)(nt * 128 + br1) * DD + kc * 32 + bc1 * 8);
        }

        if (act) {
            #pragma unroll
            for (int kp = 0; kp < 16; ++kp) {
                half2 a2[8], b2[8];
                uint4 ua0 = *(const uint4*)&sm.tb.A[kp][ty * 8];
                uint4 ua1 = *(const uint4*)&sm.tb.A[kp][ty * 8 + 4];
                uint4 ub0 = *(const uint4*)&sm.tb.B[kp][tx * 8];
                uint4 ub1 = *(const uint4*)&sm.tb.B[kp][tx * 8 + 4];
                const half2* ap0 = (const half2*)&ua0; const half2* ap1 = (const half2*)&ua1;
                const half2* bp0 = (const half2*)&ub0; const half2* bp1 = (const half2*)&ub1;
                #pragma unroll
                for (int i = 0; i < 4; i++) { a2[i] = ap0[i]; a2[i+4] = ap1[i]; b2[i] = bp0[i]; b2[i+4] = bp1[i]; }
                #pragma unroll
                for (int i = 0; i < 8; i++)
                    #pragma unroll
                    for (int j = 0; j < 8; j++)
                        acc[i][j] = __hfma2(a2[i], b2[j], acc[i][j]);
            }

            if ((g & 15) == 15) {   // end of code tile: store dists, fold min, reset
                int nt = g >> 4;
                int col0 = nt * 128 + tx * 8;
                #pragma unroll
                for (int i = 0; i < 8; i++) {
                    int row = row0 + ty * 8 + i;
                    float dd[8];
                    #pragma unroll
                    for (int j = 0; j < 8; j++) {
                        half2 sv = acc[i][j];
                        float dot = __low2float(sv) + __high2float(sv);
                        dd[j] = __ldg(cn + col0 + j) - 2.0f * dot;
                        d1[i] = fminf(d1[i], dd[j]);
                        acc[i][j] = __float2half2_rn(0.f);
                    }
                    if (row < NTOK) {
                        float* dp = g_dist + (size_t)row * KK_CB + col0;
                        *(float4*)(dp)     = make_float4(dd[0], dd[1], dd[2], dd[3]);
                        *(float4*)(dp + 4) = make_float4(dd[4], dd[5], dd[6], dd[7]);
                    }
                }
            }
        }
        __syncthreads();
    }

    // cross-tx min reduce -> g_d1
    if (act) {
        #pragma unroll
        for (int i = 0; i < 8; i++) sm.red.d[ty * 8 + i][tx] = d1[i];
    }
    __syncthreads();
    if (t < MTILE) {
        float m = sm.red.d[t][0];
        #pragma unroll
        for (int j = 1; j < 16; j++) m = fminf(m, sm.red.d[t][j]);
        int tok = row0 + t;
        if (tok < NTOK) g_d1[tok] = m;
    }
}

// ---------------- rescue: exact fp32 rescore of codes within MARGIN of approx min ----------------
__global__ void rescue_kernel(const float* __restrict__ x,
                              const float* __restrict__ cb, int stage) {
    int tok  = blockIdx.x * 8 + (threadIdx.x >> 5);
    int lane = threadIdx.x & 31;
    if (tok >= NTOK) return;

    const float* __restrict__ dist = g_dist + (size_t)tok * KK_CB;
    float thr = g_d1[tok] + MARGIN;

    const float* r = (stage == 0) ? (x + (size_t)tok * DD) : (g_residual + (size_t)tok * DD);
    float rv[16];
    #pragma unroll
    for (int i = 0; i < 16; ++i) rv[i] = r[lane + 32 * i];

    const float* cbs = cb + (size_t)stage * KK_CB * DD;
    const float* cnp = g_cnorm + stage * KK_CB;

    float bd = 3.4e38f; int bk = 0;
    for (int j0 = 0; j0 < KK_CB; j0 += 32) {
        float dv = dist[j0 + lane];
        unsigned mask = __ballot_sync(0xffffffffu, dv <= thr);
        while (mask) {
            int j = j0 + __ffs(mask) - 1;
            mask &= mask - 1;
            const float* c = cbs + (size_t)j * DD;
            float s = 0.f;
            #pragma unroll
            for (int i = 0; i < 16; ++i) s += rv[i] * c[lane + 32 * i];
            #pragma unroll
            for (int o = 16; o > 0; o >>= 1) s += __shfl_xor_sync(0xffffffffu, s, o);
            float de = __ldg(cnp + j) - 2.0f * s;
            if (de < bd) { bd = de; bk = j; }   // ascending j => first-min tie-break
        }
    }
    if (lane == 0) g_idx[stage * NTOK + tok] = bk;
}

// ---------------- residual update (exact fp32) + fp16 mirror + loss + stage-3 quant ----------------
__global__ void update_kernel(const float* __restrict__ x,
                              const float* __restrict__ cb_stage,
                              float* __restrict__ quant, int stage) {
    __shared__ float sred[256];
    const float4* src = (const float4*)((stage == 0) ? x : g_residual);
    float4* res = (float4*)g_residual;
    const float4* cb4 = (const float4*)cb_stage;
    const float4* x4  = (const float4*)x;
    float4* q4 = (float4*)quant;
    const int* idx = g_idx + stage * NTOK;

    float lsum = 0.f;
    int n4 = NELEM / 4;
    for (int e = blockIdx.x * blockDim.x + threadIdx.x; e < n4; e += gridDim.x * blockDim.x) {
        int tok = e >> 7;
        int d4  = e & 127;
        int k   = __ldg(idx + tok);
        float4 r = src[e];
        float4 q = cb4[(size_t)k * 128 + d4];
        float nx = r.x - q.x, ny = r.y - q.y, nz = r.z - q.z, nw = r.w - q.w;
        lsum += nx * nx + ny * ny + nz * nz + nw * nw;
        res[e] = make_float4(nx, ny, nz, nw);
        if (stage < QQ - 1) {
            *(half2*)&g_r16[e * 4]     = __floats2half2_rn(nx, ny);
            *(half2*)&g_r16[e * 4 + 2] = __floats2half2_rn(nz, nw);
        } else {
            float4 xv = x4[e];
            q4[e] = make_float4(xv.x - nx, xv.y - ny, xv.z - nz, xv.w - nw);
        }
    }
    sred[threadIdx.x] = lsum;
    __syncthreads();
    for (int o = 128; o > 0; o >>= 1) {
        if (threadIdx.x < o) sred[threadIdx.x] += sred[threadIdx.x + o];
        __syncthreads();
    }
    if (threadIdx.x == 0) atomicAdd(&g_loss, (double)sred[0]);
}

// ---------------- gather + sum + GELU: y[t] = GELU( sum over 20 table rows ) ----------------
__global__ __launch_bounds__(128)
void gather_gelu(float* __restrict__ y) {
    __shared__ int rows[20];
    int t = blockIdx.x;                  // output token 0..16383
    int b = t >> 11, to = t & (TOUT - 1);
    if (threadIdx.x < 20) {
        int kk = threadIdx.x >> 2, s = threadIdx.x & 3;
        int tin = 2 * to + kk - 1;
        rows[threadIdx.x] = ((unsigned)tin < (unsigned)TT)
            ? (kk * 4096 + s * 1024 + g_idx[s * NTOK + b * TT + tin]) : -1;
    }
    __syncthreads();
    int d4 = threadIdx.x;                // 0..127
    float ax = 0.f, ay = 0.f, az = 0.f, aw = 0.f;
    #pragma unroll
    for (int j = 0; j < 20; j++) {
        int r = rows[j];
        if (r >= 0) {
            float4 v = *(const float4*)(g_table + (size_t)r * DD + d4 * 4);
            ax += v.x; ay += v.y; az += v.z; aw += v.w;
        }
    }
    float4 o;
    o.x = 0.5f * ax * (1.0f + erff(ax * 0.70710678118654752f));
    o.y = 0.5f * ay * (1.0f + erff(ay * 0.70710678118654752f));
    o.z = 0.5f * az * (1.0f + erff(az * 0.70710678118654752f));
    o.w = 0.5f * aw * (1.0f + erff(aw * 0.70710678118654752f));
    *(float4*)(y + (size_t)t * DD + d4 * 4) = o;
}

// ---------------- indices (as float) + loss ----------------
__global__ void finalize_kernel(float* __restrict__ out) {
    int i = blockIdx.x * blockDim.x + threadIdx.x;
    if (i < IDX_SZ) out[Y_SZ + QO_SZ + i] = (float)g_idx[i];
    if (i == 0)     out[LOSS_OFF] = (float)(0.25 * g_loss / (double)NELEM);
}

// ---------------- launch ----------------
extern "C" void kernel_launch(void* const* d_in, const int* in_sizes, int n_in,
                              void* d_out, int out_size) {
    const float* x  = (const float*)d_in[0];
    const float* cb = (const float*)d_in[1];
    const float* w  = (const float*)d_in[2];
    float* out   = (float*)d_out;
    float* y     = out;
    float* quant = out + Y_SZ;

    cnorm_kernel<<<(QQ * KK_CB * 32 + 255) / 256, 256>>>(cb);
    tohalf_x<<<2048, 256>>>(x);
    tohalf_cb<<<1024, 256>>>(cb);
    tableg_kernel<<<dim3(32, 4, 5), 256>>>(cb, w);   // conv table (independent of VQ)

    for (int s = 0; s < QQ; ++s) {
        screen_kernel<<<NGRID, 256>>>(s);
        rescue_kernel<<<NTOK / 8, 256>>>(x, cb, s);
        update_kernel<<<2048, 256>>>(x, cb + (size_t)s * KK_CB * DD, quant, s);
    }
    gather_gelu<<<BB * TOUT, 128>>>(y);
    finalize_kernel<<<(IDX_SZ + 255) / 256, 256>>>(out);
}

// round 9
// speedup vs baseline: 3.0267x; 1.0743x over previous
#include <cuda_runtime.h>
#include <cuda_fp16.h>
#include <math.h>
#include <stdint.h>

// ---------------- problem constants ----------------
#define BB      8
#define TT      4096
#define DD      512
#define QQ      4
#define KK_CB   1024
#define KER     5
#define TOUT    2048
#define NTOK    32768
#define NELEM   (NTOK * DD)              // 16777216
#define Y_SZ    (BB * TOUT * DD)         // 8388608
#define QO_SZ   NELEM
#define IDX_SZ  (QQ * NTOK)
#define LOSS_OFF (Y_SZ + QO_SZ + IDX_SZ)
#define MARGIN  4.0f
#define MTILE   112
#define NGRID   ((NTOK + MTILE - 1) / MTILE)   // 293

// ---------------- persistent scratch ----------------
__device__ float  g_residual[NELEM];            // exact fp32 residual
__device__ __half g_r16[NELEM];                 // fp16 mirror for screening
__device__ __half g_cb16[QQ * KK_CB * DD];      // fp16 codebooks
__device__ __half g_dist16[(size_t)NTOK * KK_CB]; // approx distances (64 MB)
__device__ float  g_table[(size_t)KER * 4096 * DD]; // U[kk][s*1024+code][dout] (42 MB)
__device__ float  g_cnorm[QQ * KK_CB];
__device__ float  g_d1[NTOK];
__device__ int    g_idx[QQ * NTOK];
__device__ double g_loss;

// ---------------- prep kernels ----------------
__global__ void cnorm_kernel(const float* __restrict__ cb) {
    if (blockIdx.x == 0 && threadIdx.x == 0) g_loss = 0.0;
    int w    = (blockIdx.x * blockDim.x + threadIdx.x) >> 5;
    int lane = threadIdx.x & 31;
    if (w >= QQ * KK_CB) return;
    const float* c = cb + (size_t)w * DD;
    float s = 0.f;
    #pragma unroll
    for (int d = lane; d < DD; d += 32) { float v = c[d]; s += v * v; }
    #pragma unroll
    for (int o = 16; o > 0; o >>= 1) s += __shfl_down_sync(0xffffffffu, s, o);
    if (lane == 0) g_cnorm[w] = s;
}
__global__ void tohalf_x(const float* __restrict__ x) {
    for (int e = blockIdx.x * blockDim.x + threadIdx.x; e < NELEM; e += gridDim.x * blockDim.x)
        g_r16[e] = __float2half(x[e]);
}
__global__ void tohalf_cb(const float* __restrict__ cb) {
    int n = QQ * KK_CB * DD;
    for (int e = blockIdx.x * blockDim.x + threadIdx.x; e < n; e += gridDim.x * blockDim.x)
        g_cb16[e] = __float2half(cb[e]);
}

// ---------------- conv table GEMM: U[kk][code][dout] = sum_din cb[code][din]*W[kk][din][dout] ----------------
__global__ __launch_bounds__(256)
void tableg_kernel(const float* __restrict__ cb,
                   const float* __restrict__ W) {
    __shared__ __align__(16) float As[16][132];
    __shared__ __align__(16) float Bs[16][132];

    int t  = threadIdx.x;
    int tx = t & 15, ty = t >> 4;
    int crow0 = blockIdx.x * 128;
    int ncol0 = blockIdx.y * 128;
    int kk    = blockIdx.z;

    const float* Wk = W + (size_t)kk * DD * DD;

    float acc[8][8];
    #pragma unroll
    for (int i = 0; i < 8; i++)
        #pragma unroll
        for (int j = 0; j < 8; j++) acc[i][j] = 0.f;

    for (int c0 = 0; c0 < DD; c0 += 16) {
        #pragma unroll
        for (int i = 0; i < 2; i++) {
            int idx = t + 256 * i;
            int r = idx >> 2, c = idx & 3;
            float4 va = *(const float4*)(cb + (size_t)(crow0 + r) * DD + c0 + 4 * c);
            As[4*c+0][r] = va.x; As[4*c+1][r] = va.y;
            As[4*c+2][r] = va.z; As[4*c+3][r] = va.w;
            int ci = idx >> 5, cq = idx & 31;
            float4 vb = *(const float4*)(Wk + (size_t)(c0 + ci) * DD + ncol0 + cq * 4);
            *(float4*)&Bs[ci][cq * 4] = vb;
        }
        __syncthreads();
        #pragma unroll
        for (int kki = 0; kki < 16; ++kki) {
            float a[8], b[8];
            *(float4*)(a)     = *(const float4*)&As[kki][ty * 8];
            *(float4*)(a + 4) = *(const float4*)&As[kki][ty * 8 + 4];
            *(float4*)(b)     = *(const float4*)&Bs[kki][tx * 8];
            *(float4*)(b + 4) = *(const float4*)&Bs[kki][tx * 8 + 4];
            #pragma unroll
            for (int i = 0; i < 8; i++)
                #pragma unroll
                for (int j = 0; j < 8; j++) acc[i][j] += a[i] * b[j];
        }
        __syncthreads();
    }
    #pragma unroll
    for (int i = 0; i < 8; i++) {
        int row = crow0 + ty * 8 + i;
        float* dst = g_table + ((size_t)kk * 4096 + row) * DD + ncol0 + tx * 8;
        *(float4*)(dst)     = make_float4(acc[i][0], acc[i][1], acc[i][2], acc[i][3]);
        *(float4*)(dst + 4) = make_float4(acc[i][4], acc[i][5], acc[i][6], acc[i][7]);
    }
}

// ---------------- fp16 screening GEMM (M-tile 112, fp16 dist store) ----------------
__global__ __launch_bounds__(256, 2)
void screen_kernel(int stage) {
    __shared__ union {
        struct { __align__(16) uint32_t A[16][116]; __align__(16) uint32_t B[16][132]; } tb;
        struct { float d[MTILE][17]; } red;
    } sm;

    int t  = threadIdx.x;
    int tx = t & 15, ty = t >> 4;
    int row0 = blockIdx.x * MTILE;
    bool act = (ty < 14);

    const __half* __restrict__ Ab = g_r16;
    const __half* __restrict__ Bb = g_cb16 + (size_t)stage * KK_CB * DD;
    const float*  __restrict__ cn = g_cnorm + stage * KK_CB;

    half2 acc[8][8];
    #pragma unroll
    for (int i = 0; i < 8; i++)
        #pragma unroll
        for (int j = 0; j < 8; j++) acc[i][j] = __float2half2_rn(0.f);

    float d1[8];
    #pragma unroll
    for (int i = 0; i < 8; i++) d1[i] = 3.4e38f;

    int ar0 = t >> 2,           ac0 = t & 3;
    int ar1 = (t + 256) >> 2,   ac1 = (t + 256) & 3;
    bool a1v = (ar1 < MTILE);
    int ar1c = a1v ? ar1 : 0;
    int br0 = ar0, bc0 = ac0;
    int br1 = ar1 & 127, bc1 = ac1;
    int tokA0 = min(row0 + ar0, NTOK - 1);
    int tokA1 = min(row0 + ar1c, NTOK - 1);

    uint4 pa0, pa1, pb0, pb1;
    pa0 = *(const uint4*)(Ab + (size_t)tokA0 * DD + ac0 * 8);
    pa1 = *(const uint4*)(Ab + (size_t)tokA1 * DD + ac1 * 8);
    pb0 = *(const uint4*)(Bb + (size_t)br0 * DD + bc0 * 8);
    pb1 = *(const uint4*)(Bb + (size_t)br1 * DD + bc1 * 8);

    for (int g = 0; g < 128; ++g) {
        {
            const uint32_t* w0 = (const uint32_t*)&pa0;
            const uint32_t* w1 = (const uint32_t*)&pa1;
            const uint32_t* v0 = (const uint32_t*)&pb0;
            const uint32_t* v1 = (const uint32_t*)&pb1;
            #pragma unroll
            for (int j = 0; j < 4; j++) {
                sm.tb.A[4*ac0 + j][ar0] = w0[j];
                if (a1v) sm.tb.A[4*ac1 + j][ar1] = w1[j];
                sm.tb.B[4*bc0 + j][br0] = v0[j];
                sm.tb.B[4*bc1 + j][br1] = v1[j];
            }
        }
        __syncthreads();

        if (g < 127) {
            int ng = g + 1;
            int nt = ng >> 4, kc = ng & 15;
            pa0 = *(const uint4*)(Ab + (size_t)tokA0 * DD + kc * 32 + ac0 * 8);
            pa1 = *(const uint4*)(Ab + (size_t)tokA1 * DD + kc * 32 + ac1 * 8);
            pb0 = *(const uint4*)(Bb + (size_t)(nt * 128 + br0) * DD + kc * 32 + bc0 * 8);
            pb1 = *(const uint4*)(Bb + (size_t)(nt * 128 + br1) * DD + kc * 32 + bc1 * 8);
        }

        if (act) {
            #pragma unroll
            for (int kp = 0; kp < 16; ++kp) {
                half2 a2[8], b2[8];
                uint4 ua0 = *(const uint4*)&sm.tb.A[kp][ty * 8];
                uint4 ua1 = *(const uint4*)&sm.tb.A[kp][ty * 8 + 4];
                uint4 ub0 = *(const uint4*)&sm.tb.B[kp][tx * 8];
                uint4 ub1 = *(const uint4*)&sm.tb.B[kp][tx * 8 + 4];
                const half2* ap0 = (const half2*)&ua0; const half2* ap1 = (const half2*)&ua1;
                const half2* bp0 = (const half2*)&ub0; const half2* bp1 = (const half2*)&ub1;
                #pragma unroll
                for (int i = 0; i < 4; i++) { a2[i] = ap0[i]; a2[i+4] = ap1[i]; b2[i] = bp0[i]; b2[i+4] = bp1[i]; }
                #pragma unroll
                for (int i = 0; i < 8; i++)
                    #pragma unroll
                    for (int j = 0; j < 8; j++)
                        acc[i][j] = __hfma2(a2[i], b2[j], acc[i][j]);
            }

            if ((g & 15) == 15) {   // end of code tile: store fp16 dists, fold min, reset
                int nt = g >> 4;
                int col0 = nt * 128 + tx * 8;
                #pragma unroll
                for (int i = 0; i < 8; i++) {
                    int row = row0 + ty * 8 + i;
                    float dd[8];
                    #pragma unroll
                    for (int j = 0; j < 8; j++) {
                        half2 sv = acc[i][j];
                        float dot = __low2float(sv) + __high2float(sv);
                        dd[j] = __ldg(cn + col0 + j) - 2.0f * dot;
                        d1[i] = fminf(d1[i], dd[j]);
                        acc[i][j] = __float2half2_rn(0.f);
                    }
                    if (row < NTOK) {
                        uint4 pk;
                        half2* ph = (half2*)&pk;
                        ph[0] = __floats2half2_rn(dd[0], dd[1]);
                        ph[1] = __floats2half2_rn(dd[2], dd[3]);
                        ph[2] = __floats2half2_rn(dd[4], dd[5]);
                        ph[3] = __floats2half2_rn(dd[6], dd[7]);
                        *(uint4*)(g_dist16 + (size_t)row * KK_CB + col0) = pk;
                    }
                }
            }
        }
        __syncthreads();
    }

    if (act) {
        #pragma unroll
        for (int i = 0; i < 8; i++) sm.red.d[ty * 8 + i][tx] = d1[i];
    }
    __syncthreads();
    if (t < MTILE) {
        float m = sm.red.d[t][0];
        #pragma unroll
        for (int j = 1; j < 16; j++) m = fminf(m, sm.red.d[t][j]);
        int tok = row0 + t;
        if (tok < NTOK) g_d1[tok] = m;
    }
}

// ---------------- fused rescue + residual update, warp-per-token ----------------
__global__ __launch_bounds__(256)
void rescue_update_kernel(const float* __restrict__ x,
                          const float* __restrict__ cb,
                          float* __restrict__ quant, int stage) {
    __shared__ float s_l[8];
    int warp = threadIdx.x >> 5, lane = threadIdx.x & 31;
    int tok  = blockIdx.x * 8 + warp;

    const __half* __restrict__ dist = g_dist16 + (size_t)tok * KK_CB;
    float thr = g_d1[tok] + MARGIN;

    const float* r = (stage == 0) ? (x + (size_t)tok * DD) : (g_residual + (size_t)tok * DD);
    float rv[16];
    #pragma unroll
    for (int i = 0; i < 16; ++i) rv[i] = r[lane + 32 * i];

    const float* cbs = cb + (size_t)stage * KK_CB * DD;
    const float* cnp = g_cnorm + stage * KK_CB;

    // exact rescore of candidates (ascending j => first-min tie-break)
    float bd = 3.4e38f; int bk = 0;
    for (int j0 = 0; j0 < KK_CB; j0 += 32) {
        float dv = __half2float(dist[j0 + lane]);
        unsigned mask = __ballot_sync(0xffffffffu, dv <= thr);
        while (mask) {
            int j = j0 + __ffs(mask) - 1;
            mask &= mask - 1;
            const float* c = cbs + (size_t)j * DD;
            float s = 0.f;
            #pragma unroll
            for (int i = 0; i < 16; ++i) s += rv[i] * c[lane + 32 * i];
            #pragma unroll
            for (int o = 16; o > 0; o >>= 1) s += __shfl_xor_sync(0xffffffffu, s, o);
            float de = __ldg(cnp + j) - 2.0f * s;
            if (de < bd) { bd = de; bk = j; }
        }
    }
    if (lane == 0) g_idx[stage * NTOK + tok] = bk;

    // fused update using rv in registers
    const float* c = cbs + (size_t)bk * DD;
    float lsum = 0.f;
    if (stage < QQ - 1) {
        float* res = g_residual + (size_t)tok * DD;
        __half* r16 = g_r16 + (size_t)tok * DD;
        #pragma unroll
        for (int i = 0; i < 16; ++i) {
            int d = lane + 32 * i;
            float nv = rv[i] - c[d];
            lsum += nv * nv;
            res[d] = nv;
            r16[d] = __float2half(nv);
        }
    } else {
        const float* xr = x + (size_t)tok * DD;
        float* q = quant + (size_t)tok * DD;
        #pragma unroll
        for (int i = 0; i < 16; ++i) {
            int d = lane + 32 * i;
            float nv = rv[i] - c[d];
            lsum += nv * nv;
            q[d] = xr[d] - nv;
        }
    }
    #pragma unroll
    for (int o = 16; o > 0; o >>= 1) lsum += __shfl_down_sync(0xffffffffu, lsum, o);
    if (lane == 0) s_l[warp] = lsum;
    __syncthreads();
    if (threadIdx.x == 0) {
        float s = 0.f;
        #pragma unroll
        for (int i = 0; i < 8; i++) s += s_l[i];
        atomicAdd(&g_loss, (double)s);
    }
}

// ---------------- gather + sum + GELU ----------------
__global__ __launch_bounds__(128)
void gather_gelu(float* __restrict__ y) {
    __shared__ int rows[20];
    int t = blockIdx.x;
    int b = t >> 11, to = t & (TOUT - 1);
    if (threadIdx.x < 20) {
        int kk = threadIdx.x >> 2, s = threadIdx.x & 3;
        int tin = 2 * to + kk - 1;
        rows[threadIdx.x] = ((unsigned)tin < (unsigned)TT)
            ? (kk * 4096 + s * 1024 + g_idx[s * NTOK + b * TT + tin]) : -1;
    }
    __syncthreads();
    int d4 = threadIdx.x;
    float ax = 0.f, ay = 0.f, az = 0.f, aw = 0.f;
    #pragma unroll
    for (int j = 0; j < 20; j++) {
        int r = rows[j];
        if (r >= 0) {
            float4 v = *(const float4*)(g_table + (size_t)r * DD + d4 * 4);
            ax += v.x; ay += v.y; az += v.z; aw += v.w;
        }
    }
    float4 o;
    o.x = 0.5f * ax * (1.0f + erff(ax * 0.70710678118654752f));
    o.y = 0.5f * ay * (1.0f + erff(ay * 0.70710678118654752f));
    o.z = 0.5f * az * (1.0f + erff(az * 0.70710678118654752f));
    o.w = 0.5f * aw * (1.0f + erff(aw * 0.70710678118654752f));
    *(float4*)(y + (size_t)t * DD + d4 * 4) = o;
}

// ---------------- indices (as float) + loss ----------------
__global__ void finalize_kernel(float* __restrict__ out) {
    int i = blockIdx.x * blockDim.x + threadIdx.x;
    if (i < IDX_SZ) out[Y_SZ + QO_SZ + i] = (float)g_idx[i];
    if (i == 0)     out[LOSS_OFF] = (float)(0.25 * g_loss / (double)NELEM);
}

// ---------------- launch ----------------
extern "C" void kernel_launch(void* const* d_in, const int* in_sizes, int n_in,
                              void* d_out, int out_size) {
    const float* x  = (const float*)d_in[0];
    const float* cb = (const float*)d_in[1];
    const float* w  = (const float*)d_in[2];
    float* out   = (float*)d_out;
    float* y     = out;
    float* quant = out + Y_SZ;

    cnorm_kernel<<<(QQ * KK_CB * 32 + 255) / 256, 256>>>(cb);
    tohalf_x<<<2048, 256>>>(x);
    tohalf_cb<<<1024, 256>>>(cb);
    tableg_kernel<<<dim3(32, 4, 5), 256>>>(cb, w);

    for (int s = 0; s < QQ; ++s) {
        screen_kernel<<<NGRID, 256>>>(s);
        rescue_update_kernel<<<NTOK / 8, 256>>>(x, cb, quant, s);
    }
    gather_gelu<<<BB * TOUT, 128>>>(y);
    finalize_kernel<<<(IDX_SZ + 255) / 256, 256>>>(out);
}

// round 10
// speedup vs baseline: 3.1080x; 1.0269x over previous
#include <cuda_runtime.h>
#include <cuda_fp16.h>
#include <math.h>
#include <stdint.h>

// ---------------- problem constants ----------------
#define BB      8
#define TT      4096
#define DD      512
#define QQ      4
#define KK_CB   1024
#define KER     5
#define TOUT    2048
#define NTOK    32768
#define NELEM   (NTOK * DD)              // 16777216
#define Y_SZ    (BB * TOUT * DD)         // 8388608
#define QO_SZ   NELEM
#define IDX_SZ  (QQ * NTOK)
#define LOSS_OFF (Y_SZ + QO_SZ + IDX_SZ)
#define MARGIN  4.0f
#define MTILE   112
#define NGRID   ((NTOK + MTILE - 1) / MTILE)   // 293

// ---------------- persistent scratch ----------------
__device__ float  g_residual[NELEM];            // exact fp32 residual
__device__ __half g_r16[NELEM];                 // fp16 mirror for screening
__device__ __half g_cb16[QQ * KK_CB * DD];      // fp16 codebooks
__device__ __half g_dist16[(size_t)NTOK * KK_CB]; // approx distances (64 MB)
__device__ float  g_table[(size_t)KER * 4096 * DD]; // U[kk][s*1024+code][dout] (42 MB)
__device__ float  g_cnorm[QQ * KK_CB];
__device__ float  g_d1[NTOK];
__device__ int    g_idx[QQ * NTOK];
__device__ double g_loss;

// ---------------- prep kernels ----------------
__global__ void cnorm_kernel(const float* __restrict__ cb) {
    if (blockIdx.x == 0 && threadIdx.x == 0) g_loss = 0.0;
    int w    = (blockIdx.x * blockDim.x + threadIdx.x) >> 5;
    int lane = threadIdx.x & 31;
    if (w >= QQ * KK_CB) return;
    const float* c = cb + (size_t)w * DD;
    float s = 0.f;
    #pragma unroll
    for (int d = lane; d < DD; d += 32) { float v = c[d]; s += v * v; }
    #pragma unroll
    for (int o = 16; o > 0; o >>= 1) s += __shfl_down_sync(0xffffffffu, s, o);
    if (lane == 0) g_cnorm[w] = s;
}
__global__ void tohalf_x(const float* __restrict__ x) {
    for (int e = blockIdx.x * blockDim.x + threadIdx.x; e < NELEM; e += gridDim.x * blockDim.x)
        g_r16[e] = __float2half(x[e]);
}
__global__ void tohalf_cb(const float* __restrict__ cb) {
    int n = QQ * KK_CB * DD;
    for (int e = blockIdx.x * blockDim.x + threadIdx.x; e < n; e += gridDim.x * blockDim.x)
        g_cb16[e] = __float2half(cb[e]);
}

// ---------------- conv table GEMM: U[kk][code][dout] = sum_din cb[code][din]*W[kk][din][dout] ----------------
__global__ __launch_bounds__(256)
void tableg_kernel(const float* __restrict__ cb,
                   const float* __restrict__ W) {
    __shared__ __align__(16) float As[16][132];
    __shared__ __align__(16) float Bs[16][132];

    int t  = threadIdx.x;
    int tx = t & 15, ty = t >> 4;
    int crow0 = blockIdx.x * 128;
    int ncol0 = blockIdx.y * 128;
    int kk    = blockIdx.z;

    const float* Wk = W + (size_t)kk * DD * DD;

    float acc[8][8];
    #pragma unroll
    for (int i = 0; i < 8; i++)
        #pragma unroll
        for (int j = 0; j < 8; j++) acc[i][j] = 0.f;

    for (int c0 = 0; c0 < DD; c0 += 16) {
        #pragma unroll
        for (int i = 0; i < 2; i++) {
            int idx = t + 256 * i;
            int r = idx >> 2, c = idx & 3;
            float4 va = *(const float4*)(cb + (size_t)(crow0 + r) * DD + c0 + 4 * c);
            As[4*c+0][r] = va.x; As[4*c+1][r] = va.y;
            As[4*c+2][r] = va.z; As[4*c+3][r] = va.w;
            int ci = idx >> 5, cq = idx & 31;
            float4 vb = *(const float4*)(Wk + (size_t)(c0 + ci) * DD + ncol0 + cq * 4);
            *(float4*)&Bs[ci][cq * 4] = vb;
        }
        __syncthreads();
        #pragma unroll
        for (int kki = 0; kki < 16; ++kki) {
            float a[8], b[8];
            *(float4*)(a)     = *(const float4*)&As[kki][ty * 8];
            *(float4*)(a + 4) = *(const float4*)&As[kki][ty * 8 + 4];
            *(float4*)(b)     = *(const float4*)&Bs[kki][tx * 8];
            *(float4*)(b + 4) = *(const float4*)&Bs[kki][tx * 8 + 4];
            #pragma unroll
            for (int i = 0; i < 8; i++)
                #pragma unroll
                for (int j = 0; j < 8; j++) acc[i][j] += a[i] * b[j];
        }
        __syncthreads();
    }
    #pragma unroll
    for (int i = 0; i < 8; i++) {
        int row = crow0 + ty * 8 + i;
        float* dst = g_table + ((size_t)kk * 4096 + row) * DD + ncol0 + tx * 8;
        *(float4*)(dst)     = make_float4(acc[i][0], acc[i][1], acc[i][2], acc[i][3]);
        *(float4*)(dst + 4) = make_float4(acc[i][4], acc[i][5], acc[i][6], acc[i][7]);
    }
}

// ---------------- fp16 screening GEMM (double-buffered smem, 1 barrier/iter) ----------------
__global__ __launch_bounds__(256, 2)
void screen_kernel(int stage) {
    __shared__ union {
        struct { __align__(16) uint32_t A[2][16][116]; __align__(16) uint32_t B[2][16][132]; } tb;
        struct { float d[MTILE][17]; } red;
    } sm;

    int t  = threadIdx.x;
    int tx = t & 15, ty = t >> 4;
    int row0 = blockIdx.x * MTILE;
    bool act = (ty < 14);

    const __half* __restrict__ Ab = g_r16;
    const __half* __restrict__ Bb = g_cb16 + (size_t)stage * KK_CB * DD;
    const float*  __restrict__ cn = g_cnorm + stage * KK_CB;

    half2 acc[8][8];
    #pragma unroll
    for (int i = 0; i < 8; i++)
        #pragma unroll
        for (int j = 0; j < 8; j++) acc[i][j] = __float2half2_rn(0.f);

    float d1[8];
    #pragma unroll
    for (int i = 0; i < 8; i++) d1[i] = 3.4e38f;

    int ar0 = t >> 2,           ac0 = t & 3;
    int ar1 = (t + 256) >> 2,   ac1 = (t + 256) & 3;
    bool a1v = (ar1 < MTILE);
    int ar1c = a1v ? ar1 : 0;
    int br0 = ar0, bc0 = ac0;
    int br1 = ar1 & 127, bc1 = ac1;
    int tokA0 = min(row0 + ar0, NTOK - 1);
    int tokA1 = min(row0 + ar1c, NTOK - 1);

    uint4 pa0, pa1, pb0, pb1;
    // prologue: load + store chunk 0 into buffer 0 (no barrier needed yet)
    pa0 = *(const uint4*)(Ab + (size_t)tokA0 * DD + ac0 * 8);
    pa1 = *(const uint4*)(Ab + (size_t)tokA1 * DD + ac1 * 8);
    pb0 = *(const uint4*)(Bb + (size_t)br0 * DD + bc0 * 8);
    pb1 = *(const uint4*)(Bb + (size_t)br1 * DD + bc1 * 8);
    {
        const uint32_t* w0 = (const uint32_t*)&pa0;
        const uint32_t* w1 = (const uint32_t*)&pa1;
        const uint32_t* v0 = (const uint32_t*)&pb0;
        const uint32_t* v1 = (const uint32_t*)&pb1;
        #pragma unroll
        for (int j = 0; j < 4; j++) {
            sm.tb.A[0][4*ac0 + j][ar0] = w0[j];
            if (a1v) sm.tb.A[0][4*ac1 + j][ar1] = w1[j];
            sm.tb.B[0][4*bc0 + j][br0] = v0[j];
            sm.tb.B[0][4*bc1 + j][br1] = v1[j];
        }
    }

    for (int g = 0; g < 128; ++g) {
        __syncthreads();     // buf[g&1] fully written; buf[(g+1)&1] fully drained
        int buf = g & 1;

        if (g < 127) {       // prefetch chunk g+1 into registers
            int ng = g + 1;
            int nt = ng >> 4, kc = ng & 15;
            pa0 = *(const uint4*)(Ab + (size_t)tokA0 * DD + kc * 32 + ac0 * 8);
            pa1 = *(const uint4*)(Ab + (size_t)tokA1 * DD + kc * 32 + ac1 * 8);
            pb0 = *(const uint4*)(Bb + (size_t)(nt * 128 + br0) * DD + kc * 32 + bc0 * 8);
            pb1 = *(const uint4*)(Bb + (size_t)(nt * 128 + br1) * DD + kc * 32 + bc1 * 8);
        }

        if (act) {
            #pragma unroll
            for (int kp = 0; kp < 16; ++kp) {
                half2 a2[8], b2[8];
                uint4 ua0 = *(const uint4*)&sm.tb.A[buf][kp][ty * 8];
                uint4 ua1 = *(const uint4*)&sm.tb.A[buf][kp][ty * 8 + 4];
                uint4 ub0 = *(const uint4*)&sm.tb.B[buf][kp][tx * 8];
                uint4 ub1 = *(const uint4*)&sm.tb.B[buf][kp][tx * 8 + 4];
                const half2* ap0 = (const half2*)&ua0; const half2* ap1 = (const half2*)&ua1;
                const half2* bp0 = (const half2*)&ub0; const half2* bp1 = (const half2*)&ub1;
                #pragma unroll
                for (int i = 0; i < 4; i++) { a2[i] = ap0[i]; a2[i+4] = ap1[i]; b2[i] = bp0[i]; b2[i+4] = bp1[i]; }
                #pragma unroll
                for (int i = 0; i < 8; i++)
                    #pragma unroll
                    for (int j = 0; j < 8; j++)
                        acc[i][j] = __hfma2(a2[i], b2[j], acc[i][j]);
            }

            if ((g & 15) == 15) {   // end of code tile: store fp16 dists, fold min, reset
                int nt = g >> 4;
                int col0 = nt * 128 + tx * 8;
                #pragma unroll
                for (int i = 0; i < 8; i++) {
                    int row = row0 + ty * 8 + i;
                    float dd[8];
                    #pragma unroll
                    for (int j = 0; j < 8; j++) {
                        half2 sv = acc[i][j];
                        float dot = __low2float(sv) + __high2float(sv);
                        dd[j] = __ldg(cn + col0 + j) - 2.0f * dot;
                        d1[i] = fminf(d1[i], dd[j]);
                        acc[i][j] = __float2half2_rn(0.f);
                    }
                    if (row < NTOK) {
                        uint4 pk;
                        half2* ph = (half2*)&pk;
                        ph[0] = __floats2half2_rn(dd[0], dd[1]);
                        ph[1] = __floats2half2_rn(dd[2], dd[3]);
                        ph[2] = __floats2half2_rn(dd[4], dd[5]);
                        ph[3] = __floats2half2_rn(dd[6], dd[7]);
                        *(uint4*)(g_dist16 + (size_t)row * KK_CB + col0) = pk;
                    }
                }
            }
        }

        if (g < 127) {       // store prefetched chunk into the other buffer
            int nb = (g + 1) & 1;
            const uint32_t* w0 = (const uint32_t*)&pa0;
            const uint32_t* w1 = (const uint32_t*)&pa1;
            const uint32_t* v0 = (const uint32_t*)&pb0;
            const uint32_t* v1 = (const uint32_t*)&pb1;
            #pragma unroll
            for (int j = 0; j < 4; j++) {
                sm.tb.A[nb][4*ac0 + j][ar0] = w0[j];
                if (a1v) sm.tb.A[nb][4*ac1 + j][ar1] = w1[j];
                sm.tb.B[nb][4*bc0 + j][br0] = v0[j];
                sm.tb.B[nb][4*bc1 + j][br1] = v1[j];
            }
        }
    }

    __syncthreads();
    if (act) {
        #pragma unroll
        for (int i = 0; i < 8; i++) sm.red.d[ty * 8 + i][tx] = d1[i];
    }
    __syncthreads();
    if (t < MTILE) {
        float m = sm.red.d[t][0];
        #pragma unroll
        for (int j = 1; j < 16; j++) m = fminf(m, sm.red.d[t][j]);
        int tok = row0 + t;
        if (tok < NTOK) g_d1[tok] = m;
    }
}

// ---------------- fused rescue + residual update, warp-per-token ----------------
__global__ __launch_bounds__(256)
void rescue_update_kernel(const float* __restrict__ x,
                          const float* __restrict__ cb,
                          float* __restrict__ quant, int stage) {
    __shared__ float s_l[8];
    int warp = threadIdx.x >> 5, lane = threadIdx.x & 31;
    int tok  = blockIdx.x * 8 + warp;

    const __half* __restrict__ dist = g_dist16 + (size_t)tok * KK_CB;
    float thr = g_d1[tok] + MARGIN;

    const float* r = (stage == 0) ? (x + (size_t)tok * DD) : (g_residual + (size_t)tok * DD);
    float rv[16];
    #pragma unroll
    for (int i = 0; i < 16; ++i) rv[i] = r[lane + 32 * i];

    const float* cbs = cb + (size_t)stage * KK_CB * DD;
    const float* cnp = g_cnorm + stage * KK_CB;

    float bd = 3.4e38f; int bk = 0;
    for (int j0 = 0; j0 < KK_CB; j0 += 32) {
        float dv = __half2float(dist[j0 + lane]);
        unsigned mask = __ballot_sync(0xffffffffu, dv <= thr);
        while (mask) {
            int j = j0 + __ffs(mask) - 1;
            mask &= mask - 1;
            const float* c = cbs + (size_t)j * DD;
            float s = 0.f;
            #pragma unroll
            for (int i = 0; i < 16; ++i) s += rv[i] * c[lane + 32 * i];
            #pragma unroll
            for (int o = 16; o > 0; o >>= 1) s += __shfl_xor_sync(0xffffffffu, s, o);
            float de = __ldg(cnp + j) - 2.0f * s;
            if (de < bd) { bd = de; bk = j; }
        }
    }
    if (lane == 0) g_idx[stage * NTOK + tok] = bk;

    const float* c = cbs + (size_t)bk * DD;
    float lsum = 0.f;
    if (stage < QQ - 1) {
        float* res = g_residual + (size_t)tok * DD;
        __half* r16 = g_r16 + (size_t)tok * DD;
        #pragma unroll
        for (int i = 0; i < 16; ++i) {
            int d = lane + 32 * i;
            float nv = rv[i] - c[d];
            lsum += nv * nv;
            res[d] = nv;
            r16[d] = __float2half(nv);
        }
    } else {
        const float* xr = x + (size_t)tok * DD;
        float* q = quant + (size_t)tok * DD;
        #pragma unroll
        for (int i = 0; i < 16; ++i) {
            int d = lane + 32 * i;
            float nv = rv[i] - c[d];
            lsum += nv * nv;
            q[d] = xr[d] - nv;
        }
    }
    #pragma unroll
    for (int o = 16; o > 0; o >>= 1) lsum += __shfl_down_sync(0xffffffffu, lsum, o);
    if (lane == 0) s_l[warp] = lsum;
    __syncthreads();
    if (threadIdx.x == 0) {
        float s = 0.f;
        #pragma unroll
        for (int i = 0; i < 8; i++) s += s_l[i];
        atomicAdd(&g_loss, (double)s);
    }
}

// ---------------- gather + sum + GELU ----------------
__global__ __launch_bounds__(128)
void gather_gelu(float* __restrict__ y) {
    __shared__ int rows[20];
    int t = blockIdx.x;
    int b = t >> 11, to = t & (TOUT - 1);
    if (threadIdx.x < 20) {
        int kk = threadIdx.x >> 2, s = threadIdx.x & 3;
        int tin = 2 * to + kk - 1;
        rows[threadIdx.x] = ((unsigned)tin < (unsigned)TT)
            ? (kk * 4096 + s * 1024 + g_idx[s * NTOK + b * TT + tin]) : -1;
    }
    __syncthreads();
    int d4 = threadIdx.x;
    float ax = 0.f, ay = 0.f, az = 0.f, aw = 0.f;
    #pragma unroll
    for (int j = 0; j < 20; j++) {
        int r = rows[j];
        if (r >= 0) {
            float4 v = *(const float4*)(g_table + (size_t)r * DD + d4 * 4);
            ax += v.x; ay += v.y; az += v.z; aw += v.w;
        }
    }
    float4 o;
    o.x = 0.5f * ax * (1.0f + erff(ax * 0.70710678118654752f));
    o.y = 0.5f * ay * (1.0f + erff(ay * 0.70710678118654752f));
    o.z = 0.5f * az * (1.0f + erff(az * 0.70710678118654752f));
    o.w = 0.5f * aw * (1.0f + erff(aw * 0.70710678118654752f));
    *(float4*)(y + (size_t)t * DD + d4 * 4) = o;
}

// ---------------- indices (as float) + loss ----------------
__global__ void finalize_kernel(float* __restrict__ out) {
    int i = blockIdx.x * blockDim.x + threadIdx.x;
    if (i < IDX_SZ) out[Y_SZ + QO_SZ + i] = (float)g_idx[i];
    if (i == 0)     out[LOSS_OFF] = (float)(0.25 * g_loss / (double)NELEM);
}

// ---------------- launch ----------------
extern "C" void kernel_launch(void* const* d_in, const int* in_sizes, int n_in,
                              void* d_out, int out_size) {
    const float* x  = (const float*)d_in[0];
    const float* cb = (const float*)d_in[1];
    const float* w  = (const float*)d_in[2];
    float* out   = (float*)d_out;
    float* y     = out;
    float* quant = out + Y_SZ;

    cnorm_kernel<<<(QQ * KK_CB * 32 + 255) / 256, 256>>>(cb);
    tohalf_x<<<2048, 256>>>(x);
    tohalf_cb<<<1024, 256>>>(cb);
    tableg_kernel<<<dim3(32, 4, 5), 256>>>(cb, w);

    for (int s = 0; s < QQ; ++s) {
        screen_kernel<<<NGRID, 256>>>(s);
        rescue_update_kernel<<<NTOK / 8, 256>>>(x, cb, quant, s);
    }
    gather_gelu<<<BB * TOUT, 128>>>(y);
    finalize_kernel<<<(IDX_SZ + 255) / 256, 256>>>(out);
}

// round 11
// speedup vs baseline: 3.1305x; 1.0073x over previous
#include <cuda_runtime.h>
#include <cuda_fp16.h>
#include <math.h>
#include <stdint.h>

// ---------------- problem constants ----------------
#define BB      8
#define TT      4096
#define DD      512
#define QQ      4
#define KK_CB   1024
#define KER     5
#define TOUT    2048
#define NTOK    32768
#define NELEM   (NTOK * DD)              // 16777216
#define Y_SZ    (BB * TOUT * DD)         // 8388608
#define QO_SZ   NELEM
#define IDX_SZ  (QQ * NTOK)
#define LOSS_OFF (Y_SZ + QO_SZ + IDX_SZ)
#define MARGIN  8.0f

// ---------------- persistent scratch ----------------
__device__ float    g_residual[NELEM];              // exact fp32 residual
__device__ uint32_t g_r8[NELEM / 4];                // int8 residual, packed 4/word (16 MB)
__device__ uint32_t g_cb8[QQ * KK_CB * DD / 4];     // int8 codebooks (2 MB)
__device__ float    g_sr[NTOK];                     // per-token quant scale
__device__ float    g_sc[QQ * KK_CB];               // per-code quant scale
__device__ __half   g_dist16[(size_t)NTOK * KK_CB]; // approx distances (64 MB)
__device__ float    g_table[(size_t)KER * 4096 * DD]; // conv table (42 MB)
__device__ float    g_cnorm[QQ * KK_CB];
__device__ float    g_d1[NTOK];
__device__ int      g_idx[QQ * NTOK];
__device__ double   g_loss;

// ---------------- helpers ----------------
__device__ __forceinline__ uint32_t pack4(float v0, float v1, float v2, float v3, float inv) {
    int a = __float2int_rn(v0 * inv), b = __float2int_rn(v1 * inv);
    int c = __float2int_rn(v2 * inv), d = __float2int_rn(v3 * inv);
    return (uint32_t)(a & 0xFF) | ((uint32_t)(b & 0xFF) << 8) |
           ((uint32_t)(c & 0xFF) << 16) | ((uint32_t)(d & 0xFF) << 24);
}

// ---------------- quantize codebooks + cnorm (+loss reset) ----------------
__global__ void quant_cb_kernel(const float* __restrict__ cb) {
    if (blockIdx.x == 0 && threadIdx.x == 0) g_loss = 0.0;
    int w    = (blockIdx.x * blockDim.x + threadIdx.x) >> 5;   // code row 0..4095
    int lane = threadIdx.x & 31;
    if (w >= QQ * KK_CB) return;
    const float* c = cb + (size_t)w * DD;
    float rv[16];
    float nrm = 0.f, mx = 0.f;
    #pragma unroll
    for (int i = 0; i < 16; ++i) {
        float v = c[lane * 16 + i];
        rv[i] = v; nrm += v * v; mx = fmaxf(mx, fabsf(v));
    }
    #pragma unroll
    for (int o = 16; o > 0; o >>= 1) {
        nrm += __shfl_xor_sync(0xffffffffu, nrm, o);
        mx = fmaxf(mx, __shfl_xor_sync(0xffffffffu, mx, o));
    }
    float sc = fmaxf(mx, 1e-20f) / 127.0f;
    float inv = 1.0f / sc;
    uint4 pk;
    pk.x = pack4(rv[0],  rv[1],  rv[2],  rv[3],  inv);
    pk.y = pack4(rv[4],  rv[5],  rv[6],  rv[7],  inv);
    pk.z = pack4(rv[8],  rv[9],  rv[10], rv[11], inv);
    pk.w = pack4(rv[12], rv[13], rv[14], rv[15], inv);
    *(uint4*)(g_cb8 + (size_t)w * 128 + lane * 4) = pk;
    if (lane == 0) { g_cnorm[w] = nrm; g_sc[w] = sc; }
}

// ---------------- quantize x into r8 ----------------
__global__ void quant_x_kernel(const float* __restrict__ x) {
    int tok  = (blockIdx.x * blockDim.x + threadIdx.x) >> 5;
    int lane = threadIdx.x & 31;
    if (tok >= NTOK) return;
    const float* r = x + (size_t)tok * DD;
    float rv[16];
    float mx = 0.f;
    #pragma unroll
    for (int i = 0; i < 16; ++i) { rv[i] = r[lane * 16 + i]; mx = fmaxf(mx, fabsf(rv[i])); }
    #pragma unroll
    for (int o = 16; o > 0; o >>= 1) mx = fmaxf(mx, __shfl_xor_sync(0xffffffffu, mx, o));
    float sr = fmaxf(mx, 1e-20f) / 127.0f;
    float inv = 1.0f / sr;
    uint4 pk;
    pk.x = pack4(rv[0],  rv[1],  rv[2],  rv[3],  inv);
    pk.y = pack4(rv[4],  rv[5],  rv[6],  rv[7],  inv);
    pk.z = pack4(rv[8],  rv[9],  rv[10], rv[11], inv);
    pk.w = pack4(rv[12], rv[13], rv[14], rv[15], inv);
    *(uint4*)(g_r8 + (size_t)tok * 128 + lane * 4) = pk;
    if (lane == 0) g_sr[tok] = sr;
}

// ---------------- conv table GEMM (unchanged fp32) ----------------
__global__ __launch_bounds__(256)
void tableg_kernel(const float* __restrict__ cb,
                   const float* __restrict__ W) {
    __shared__ __align__(16) float As[16][132];
    __shared__ __align__(16) float Bs[16][132];

    int t  = threadIdx.x;
    int tx = t & 15, ty = t >> 4;
    int crow0 = blockIdx.x * 128;
    int ncol0 = blockIdx.y * 128;
    int kk    = blockIdx.z;

    const float* Wk = W + (size_t)kk * DD * DD;

    float acc[8][8];
    #pragma unroll
    for (int i = 0; i < 8; i++)
        #pragma unroll
        for (int j = 0; j < 8; j++) acc[i][j] = 0.f;

    for (int c0 = 0; c0 < DD; c0 += 16) {
        #pragma unroll
        for (int i = 0; i < 2; i++) {
            int idx = t + 256 * i;
            int r = idx >> 2, c = idx & 3;
            float4 va = *(const float4*)(cb + (size_t)(crow0 + r) * DD + c0 + 4 * c);
            As[4*c+0][r] = va.x; As[4*c+1][r] = va.y;
            As[4*c+2][r] = va.z; As[4*c+3][r] = va.w;
            int ci = idx >> 5, cq = idx & 31;
            float4 vb = *(const float4*)(Wk + (size_t)(c0 + ci) * DD + ncol0 + cq * 4);
            *(float4*)&Bs[ci][cq * 4] = vb;
        }
        __syncthreads();
        #pragma unroll
        for (int kki = 0; kki < 16; ++kki) {
            float a[8], b[8];
            *(float4*)(a)     = *(const float4*)&As[kki][ty * 8];
            *(float4*)(a + 4) = *(const float4*)&As[kki][ty * 8 + 4];
            *(float4*)(b)     = *(const float4*)&Bs[kki][tx * 8];
            *(float4*)(b + 4) = *(const float4*)&Bs[kki][tx * 8 + 4];
            #pragma unroll
            for (int i = 0; i < 8; i++)
                #pragma unroll
                for (int j = 0; j < 8; j++) acc[i][j] += a[i] * b[j];
        }
        __syncthreads();
    }
    #pragma unroll
    for (int i = 0; i < 8; i++) {
        int row = crow0 + ty * 8 + i;
        float* dst = g_table + ((size_t)kk * 4096 + row) * DD + ncol0 + tx * 8;
        *(float4*)(dst)     = make_float4(acc[i][0], acc[i][1], acc[i][2], acc[i][3]);
        *(float4*)(dst + 4) = make_float4(acc[i][4], acc[i][5], acc[i][6], acc[i][7]);
    }
}

// ---------------- int8 dp4a screening GEMM (double-buffered, 1 barrier/iter) ----------------
// Tiles: 128 tokens x 128 codes, K-chunk 32 dims (32 bytes = 2x uint4 per row).
__global__ __launch_bounds__(256, 2)
void screen_kernel(int stage) {
    __shared__ union {
        struct { __align__(16) uint4 A[2][128][2]; __align__(16) uint4 B[2][128][2]; } tb; // 16 KB
        struct { float d[128][17]; } red;
    } sm;

    int t  = threadIdx.x;
    int tx = t & 15, ty = t >> 4;
    int row0 = blockIdx.x * 128;

    const uint32_t* __restrict__ Ab = g_r8;
    const uint32_t* __restrict__ Bb = g_cb8 + (size_t)stage * KK_CB * 128;
    const float*    __restrict__ cn = g_cnorm + stage * KK_CB;
    const float*    __restrict__ scs = g_sc + stage * KK_CB;

    int acc[8][8];
    #pragma unroll
    for (int i = 0; i < 8; i++)
        #pragma unroll
        for (int j = 0; j < 8; j++) acc[i][j] = 0;

    float d1[8];
    #pragma unroll
    for (int i = 0; i < 8; i++) d1[i] = 3.4e38f;

    // loader mapping: 256 threads = 128 rows x 2 halves (16B each)
    int lrow = t >> 1, lh = t & 1;
    int lchk = lh ^ ((lrow >> 3) & 1);           // XOR swizzle
    // compute-side swizzled chunk selectors
    int csA = ty & 1, csB = tx & 1;

    uint4 pa, pb;
    // prologue: chunk 0 (nt=0, kc=0) into buffer 0
    pa = *(const uint4*)(Ab + (size_t)(row0 + lrow) * 128 + lh * 4);
    pb = *(const uint4*)(Bb + (size_t)lrow * 128 + lh * 4);
    sm.tb.A[0][lrow][lchk] = pa;
    sm.tb.B[0][lrow][lchk] = pb;

    for (int g = 0; g < 128; ++g) {
        __syncthreads();
        int buf = g & 1;

        if (g < 127) {
            int ng = g + 1;
            int nt = ng >> 4, kc = ng & 15;
            pa = *(const uint4*)(Ab + (size_t)(row0 + lrow) * 128 + kc * 8 + lh * 4);
            pb = *(const uint4*)(Bb + (size_t)(nt * 128 + lrow) * 128 + kc * 8 + lh * 4);
        }

        #pragma unroll
        for (int h = 0; h < 2; ++h) {
            uint4 vb[8];
            #pragma unroll
            for (int j = 0; j < 8; j++) vb[j] = sm.tb.B[buf][tx * 8 + j][h ^ csB];
            #pragma unroll
            for (int i = 0; i < 8; i++) {
                uint4 va = sm.tb.A[buf][ty * 8 + i][h ^ csA];
                #pragma unroll
                for (int j = 0; j < 8; j++) {
                    int s = acc[i][j];
                    s = __dp4a((int)va.x, (int)vb[j].x, s);
                    s = __dp4a((int)va.y, (int)vb[j].y, s);
                    s = __dp4a((int)va.z, (int)vb[j].z, s);
                    s = __dp4a((int)va.w, (int)vb[j].w, s);
                    acc[i][j] = s;
                }
            }
        }

        if ((g & 15) == 15) {   // end of code tile: dists, fold min, reset
            int nt = g >> 4;
            int col0 = nt * 128 + tx * 8;
            float scf[8], cnf[8];
            #pragma unroll
            for (int j = 0; j < 8; j++) { scf[j] = __ldg(scs + col0 + j); cnf[j] = __ldg(cn + col0 + j); }
            #pragma unroll
            for (int i = 0; i < 8; i++) {
                int row = row0 + ty * 8 + i;
                float sri2 = 2.0f * __ldg(g_sr + row);
                float dd[8];
                #pragma unroll
                for (int j = 0; j < 8; j++) {
                    dd[j] = cnf[j] - sri2 * scf[j] * (float)acc[i][j];
                    d1[i] = fminf(d1[i], dd[j]);
                    acc[i][j] = 0;
                }
                uint4 pk;
                half2* ph = (half2*)&pk;
                ph[0] = __floats2half2_rn(dd[0], dd[1]);
                ph[1] = __floats2half2_rn(dd[2], dd[3]);
                ph[2] = __floats2half2_rn(dd[4], dd[5]);
                ph[3] = __floats2half2_rn(dd[6], dd[7]);
                *(uint4*)(g_dist16 + (size_t)row * KK_CB + col0) = pk;
            }
        }

        if (g < 127) {
            int nb = (g + 1) & 1;
            sm.tb.A[nb][lrow][lchk] = pa;
            sm.tb.B[nb][lrow][lchk] = pb;
        }
    }

    __syncthreads();
    #pragma unroll
    for (int i = 0; i < 8; i++) sm.red.d[ty * 8 + i][tx] = d1[i];
    __syncthreads();
    if (t < 128) {
        float m = sm.red.d[t][0];
        #pragma unroll
        for (int j = 1; j < 16; j++) m = fminf(m, sm.red.d[t][j]);
        g_d1[row0 + t] = m;
    }
}

// ---------------- fused rescue + residual update (lane-contiguous dims) ----------------
__global__ __launch_bounds__(256)
void rescue_update_kernel(const float* __restrict__ x,
                          const float* __restrict__ cb,
                          float* __restrict__ quant, int stage) {
    __shared__ float s_l[8];
    int warp = threadIdx.x >> 5, lane = threadIdx.x & 31;
    int tok  = blockIdx.x * 8 + warp;

    const __half* __restrict__ dist = g_dist16 + (size_t)tok * KK_CB;
    float thr = g_d1[tok] + MARGIN;

    const float* r = (stage == 0) ? (x + (size_t)tok * DD) : (g_residual + (size_t)tok * DD);
    float rv[16];
    #pragma unroll
    for (int i = 0; i < 4; ++i)
        *(float4*)(rv + 4 * i) = *(const float4*)(r + lane * 16 + 4 * i);

    const float* cbs = cb + (size_t)stage * KK_CB * DD;
    const float* cnp = g_cnorm + stage * KK_CB;

    // exact rescore of candidates (ascending j => first-min tie-break)
    float bd = 3.4e38f; int bk = 0;
    for (int j0 = 0; j0 < KK_CB; j0 += 32) {
        float dv = __half2float(dist[j0 + lane]);
        unsigned mask = __ballot_sync(0xffffffffu, dv <= thr);
        while (mask) {
            int j = j0 + __ffs(mask) - 1;
            mask &= mask - 1;
            const float* c = cbs + (size_t)j * DD + lane * 16;
            float s = 0.f;
            #pragma unroll
            for (int i = 0; i < 16; ++i) s += rv[i] * c[i];
            #pragma unroll
            for (int o = 16; o > 0; o >>= 1) s += __shfl_xor_sync(0xffffffffu, s, o);
            float de = __ldg(cnp + j) - 2.0f * s;
            if (de < bd) { bd = de; bk = j; }
        }
    }
    if (lane == 0) g_idx[stage * NTOK + tok] = bk;

    // fused update using rv in registers
    const float* c = cbs + (size_t)bk * DD + lane * 16;
    float nv[16];
    float lsum = 0.f, mx = 0.f;
    #pragma unroll
    for (int i = 0; i < 16; ++i) {
        nv[i] = rv[i] - c[i];
        lsum += nv[i] * nv[i];
        mx = fmaxf(mx, fabsf(nv[i]));
    }
    if (stage < QQ - 1) {
        float* res = g_residual + (size_t)tok * DD + lane * 16;
        #pragma unroll
        for (int i = 0; i < 4; ++i) *(float4*)(res + 4 * i) = *(float4*)(nv + 4 * i);
        #pragma unroll
        for (int o = 16; o > 0; o >>= 1) mx = fmaxf(mx, __shfl_xor_sync(0xffffffffu, mx, o));
        float sr = fmaxf(mx, 1e-20f) / 127.0f;
        float inv = 1.0f / sr;
        uint4 pk;
        pk.x = pack4(nv[0],  nv[1],  nv[2],  nv[3],  inv);
        pk.y = pack4(nv[4],  nv[5],  nv[6],  nv[7],  inv);
        pk.z = pack4(nv[8],  nv[9],  nv[10], nv[11], inv);
        pk.w = pack4(nv[12], nv[13], nv[14], nv[15], inv);
        *(uint4*)(g_r8 + (size_t)tok * 128 + lane * 4) = pk;
        if (lane == 0) g_sr[tok] = sr;
    } else {
        const float* xr = x + (size_t)tok * DD + lane * 16;
        float* q = quant + (size_t)tok * DD + lane * 16;
        #pragma unroll
        for (int i = 0; i < 16; ++i) q[i] = xr[i] - nv[i];
    }
    #pragma unroll
    for (int o = 16; o > 0; o >>= 1) lsum += __shfl_down_sync(0xffffffffu, lsum, o);
    if (lane == 0) s_l[warp] = lsum;
    __syncthreads();
    if (threadIdx.x == 0) {
        float s = 0.f;
        #pragma unroll
        for (int i = 0; i < 8; i++) s += s_l[i];
        atomicAdd(&g_loss, (double)s);
    }
}

// ---------------- gather + sum + GELU ----------------
__global__ __launch_bounds__(128)
void gather_gelu(float* __restrict__ y) {
    __shared__ int rows[20];
    int t = blockIdx.x;
    int b = t >> 11, to = t & (TOUT - 1);
    if (threadIdx.x < 20) {
        int kk = threadIdx.x >> 2, s = threadIdx.x & 3;
        int tin = 2 * to + kk - 1;
        rows[threadIdx.x] = ((unsigned)tin < (unsigned)TT)
            ? (kk * 4096 + s * 1024 + g_idx[s * NTOK + b * TT + tin]) : -1;
    }
    __syncthreads();
    int d4 = threadIdx.x;
    float ax = 0.f, ay = 0.f, az = 0.f, aw = 0.f;
    #pragma unroll
    for (int j = 0; j < 20; j++) {
        int r = rows[j];
        if (r >= 0) {
            float4 v = *(const float4*)(g_table + (size_t)r * DD + d4 * 4);
            ax += v.x; ay += v.y; az += v.z; aw += v.w;
        }
    }
    float4 o;
    o.x = 0.5f * ax * (1.0f + erff(ax * 0.70710678118654752f));
    o.y = 0.5f * ay * (1.0f + erff(ay * 0.70710678118654752f));
    o.z = 0.5f * az * (1.0f + erff(az * 0.70710678118654752f));
    o.w = 0.5f * aw * (1.0f + erff(aw * 0.70710678118654752f));
    *(float4*)(y + (size_t)t * DD + d4 * 4) = o;
}

// ---------------- indices (as float) + loss ----------------
__global__ void finalize_kernel(float* __restrict__ out) {
    int i = blockIdx.x * blockDim.x + threadIdx.x;
    if (i < IDX_SZ) out[Y_SZ + QO_SZ + i] = (float)g_idx[i];
    if (i == 0)     out[LOSS_OFF] = (float)(0.25 * g_loss / (double)NELEM);
}

// ---------------- launch ----------------
extern "C" void kernel_launch(void* const* d_in, const int* in_sizes, int n_in,
                              void* d_out, int out_size) {
    const float* x  = (const float*)d_in[0];
    const float* cb = (const float*)d_in[1];
    const float* w  = (const float*)d_in[2];
    float* out   = (float*)d_out;
    float* y     = out;
    float* quant = out + Y_SZ;

    quant_cb_kernel<<<(QQ * KK_CB * 32 + 255) / 256, 256>>>(cb);
    quant_x_kernel<<<(NTOK * 32 + 255) / 256, 256>>>(x);
    tableg_kernel<<<dim3(32, 4, 5), 256>>>(cb, w);

    for (int s = 0; s < QQ; ++s) {
        screen_kernel<<<NTOK / 128, 256>>>(s);
        rescue_update_kernel<<<NTOK / 8, 256>>>(x, cb, quant, s);
    }
    gather_gelu<<<BB * TOUT, 128>>>(y);
    finalize_kernel<<<(IDX_SZ + 255) / 256, 256>>>(out);
}

// round 12
// speedup vs baseline: 4.0777x; 1.3026x over previous
#include <cuda_runtime.h>
#include <cuda_fp16.h>
#include <math.h>
#include <stdint.h>

// ---------------- problem constants ----------------
#define BB      8
#define TT      4096
#define DD      512
#define QQ      4
#define KK_CB   1024
#define KER     5
#define TOUT    2048
#define NTOK    32768
#define NELEM   (NTOK * DD)              // 16777216
#define Y_SZ    (BB * TOUT * DD)         // 8388608
#define QO_SZ   NELEM
#define IDX_SZ  (QQ * NTOK)
#define LOSS_OFF (Y_SZ + QO_SZ + IDX_SZ)
#define MARGIN  8.0f
#define MTILE   112
#define NGRID   ((NTOK + MTILE - 1) / MTILE)   // 293

// ---------------- persistent scratch ----------------
__device__ float    g_residual[NELEM];              // exact fp32 residual
__device__ uint32_t g_r8[NELEM / 4];                // int8 residual, packed 4/word
__device__ uint32_t g_cb8[QQ * KK_CB * DD / 4];     // int8 codebooks
__device__ float    g_sr[NTOK];                     // per-token quant scale
__device__ float    g_sc[QQ * KK_CB];               // per-code quant scale
__device__ __half   g_dist16[(size_t)NTOK * KK_CB]; // approx distances (64 MB)
__device__ float    g_table[(size_t)KER * 4096 * DD]; // conv table (42 MB)
__device__ float    g_cnorm[QQ * KK_CB];
__device__ float    g_d1[NTOK];
__device__ int      g_idx[QQ * NTOK];
__device__ double   g_loss;

// ---------------- helpers ----------------
__device__ __forceinline__ uint32_t smem_u32(const void* p) {
    uint32_t a;
    asm("{ .reg .u64 t; cvta.to.shared.u64 t, %1; cvt.u32.u64 %0, t; }" : "=r"(a) : "l"(p));
    return a;
}
__device__ __forceinline__ void cp16(uint32_t s, const void* g) {
    asm volatile("cp.async.cg.shared.global [%0], [%1], 16;" :: "r"(s), "l"(g));
}
#define CP_COMMIT() asm volatile("cp.async.commit_group;" ::: "memory")
#define CP_WAIT0()  asm volatile("cp.async.wait_group 0;" ::: "memory")

__device__ __forceinline__ uint32_t pack4(float v0, float v1, float v2, float v3, float inv) {
    int a = __float2int_rn(v0 * inv), b = __float2int_rn(v1 * inv);
    int c = __float2int_rn(v2 * inv), d = __float2int_rn(v3 * inv);
    return (uint32_t)(a & 0xFF) | ((uint32_t)(b & 0xFF) << 8) |
           ((uint32_t)(c & 0xFF) << 16) | ((uint32_t)(d & 0xFF) << 24);
}

// ---------------- quantize codebooks + cnorm (+loss reset) ----------------
__global__ void quant_cb_kernel(const float* __restrict__ cb) {
    if (blockIdx.x == 0 && threadIdx.x == 0) g_loss = 0.0;
    int w    = (blockIdx.x * blockDim.x + threadIdx.x) >> 5;
    int lane = threadIdx.x & 31;
    if (w >= QQ * KK_CB) return;
    const float* c = cb + (size_t)w * DD;
    float rv[16];
    float nrm = 0.f, mx = 0.f;
    #pragma unroll
    for (int i = 0; i < 16; ++i) {
        float v = c[lane * 16 + i];
        rv[i] = v; nrm += v * v; mx = fmaxf(mx, fabsf(v));
    }
    #pragma unroll
    for (int o = 16; o > 0; o >>= 1) {
        nrm += __shfl_xor_sync(0xffffffffu, nrm, o);
        mx = fmaxf(mx, __shfl_xor_sync(0xffffffffu, mx, o));
    }
    float sc = fmaxf(mx, 1e-20f) / 127.0f;
    float inv = 1.0f / sc;
    uint4 pk;
    pk.x = pack4(rv[0],  rv[1],  rv[2],  rv[3],  inv);
    pk.y = pack4(rv[4],  rv[5],  rv[6],  rv[7],  inv);
    pk.z = pack4(rv[8],  rv[9],  rv[10], rv[11], inv);
    pk.w = pack4(rv[12], rv[13], rv[14], rv[15], inv);
    *(uint4*)(g_cb8 + (size_t)w * 128 + lane * 4) = pk;
    if (lane == 0) { g_cnorm[w] = nrm; g_sc[w] = sc; }
}

// ---------------- quantize x into r8 ----------------
__global__ void quant_x_kernel(const float* __restrict__ x) {
    int tok  = (blockIdx.x * blockDim.x + threadIdx.x) >> 5;
    int lane = threadIdx.x & 31;
    if (tok >= NTOK) return;
    const float* r = x + (size_t)tok * DD;
    float rv[16];
    float mx = 0.f;
    #pragma unroll
    for (int i = 0; i < 16; ++i) { rv[i] = r[lane * 16 + i]; mx = fmaxf(mx, fabsf(rv[i])); }
    #pragma unroll
    for (int o = 16; o > 0; o >>= 1) mx = fmaxf(mx, __shfl_xor_sync(0xffffffffu, mx, o));
    float sr = fmaxf(mx, 1e-20f) / 127.0f;
    float inv = 1.0f / sr;
    uint4 pk;
    pk.x = pack4(rv[0],  rv[1],  rv[2],  rv[3],  inv);
    pk.y = pack4(rv[4],  rv[5],  rv[6],  rv[7],  inv);
    pk.z = pack4(rv[8],  rv[9],  rv[10], rv[11], inv);
    pk.w = pack4(rv[12], rv[13], rv[14], rv[15], inv);
    *(uint4*)(g_r8 + (size_t)tok * 128 + lane * 4) = pk;
    if (lane == 0) g_sr[tok] = sr;
}

// ---------------- conv table GEMM (unchanged fp32) ----------------
__global__ __launch_bounds__(256)
void tableg_kernel(const float* __restrict__ cb,
                   const float* __restrict__ W) {
    __shared__ __align__(16) float As[16][132];
    __shared__ __align__(16) float Bs[16][132];

    int t  = threadIdx.x;
    int tx = t & 15, ty = t >> 4;
    int crow0 = blockIdx.x * 128;
    int ncol0 = blockIdx.y * 128;
    int kk    = blockIdx.z;

    const float* Wk = W + (size_t)kk * DD * DD;

    float acc[8][8];
    #pragma unroll
    for (int i = 0; i < 8; i++)
        #pragma unroll
        for (int j = 0; j < 8; j++) acc[i][j] = 0.f;

    for (int c0 = 0; c0 < DD; c0 += 16) {
        #pragma unroll
        for (int i = 0; i < 2; i++) {
            int idx = t + 256 * i;
            int r = idx >> 2, c = idx & 3;
            float4 va = *(const float4*)(cb + (size_t)(crow0 + r) * DD + c0 + 4 * c);
            As[4*c+0][r] = va.x; As[4*c+1][r] = va.y;
            As[4*c+2][r] = va.z; As[4*c+3][r] = va.w;
            int ci = idx >> 5, cq = idx & 31;
            float4 vb = *(const float4*)(Wk + (size_t)(c0 + ci) * DD + ncol0 + cq * 4);
            *(float4*)&Bs[ci][cq * 4] = vb;
        }
        __syncthreads();
        #pragma unroll
        for (int kki = 0; kki < 16; ++kki) {
            float a[8], b[8];
            *(float4*)(a)     = *(const float4*)&As[kki][ty * 8];
            *(float4*)(a + 4) = *(const float4*)&As[kki][ty * 8 + 4];
            *(float4*)(b)     = *(const float4*)&Bs[kki][tx * 8];
            *(float4*)(b + 4) = *(const float4*)&Bs[kki][tx * 8 + 4];
            #pragma unroll
            for (int i = 0; i < 8; i++)
                #pragma unroll
                for (int j = 0; j < 8; j++) acc[i][j] += a[i] * b[j];
        }
        __syncthreads();
    }
    #pragma unroll
    for (int i = 0; i < 8; i++) {
        int row = crow0 + ty * 8 + i;
        float* dst = g_table + ((size_t)kk * 4096 + row) * DD + ncol0 + tx * 8;
        *(float4*)(dst)     = make_float4(acc[i][0], acc[i][1], acc[i][2], acc[i][3]);
        *(float4*)(dst + 4) = make_float4(acc[i][4], acc[i][5], acc[i][6], acc[i][7]);
    }
}

// ---------------- int8 dp4a screen: conflict-free smem, cp.async, MTILE 112 ----------------
// Layout: A[buf][half16][row], B[buf][half16][row]; thread tx owns codes tx+16*j.
__global__ __launch_bounds__(256, 2)
void screen_kernel(int stage) {
    __shared__ union {
        struct { __align__(16) uint4 A[2][2][MTILE]; __align__(16) uint4 B[2][2][128]; } tb;
        struct { float d[MTILE][17]; } red;
    } sm;

    int t  = threadIdx.x;
    int tx = t & 15, ty = t >> 4;
    int row0 = blockIdx.x * MTILE;
    bool act = (ty < 14);

    const uint32_t* __restrict__ Ab = g_r8;
    const uint32_t* __restrict__ Bb = g_cb8 + (size_t)stage * KK_CB * 128;
    const float*    __restrict__ cn = g_cnorm + stage * KK_CB;
    const float*    __restrict__ scs = g_sc + stage * KK_CB;

    uint32_t sA = smem_u32(&sm.tb.A[0][0][0]);
    uint32_t sB = smem_u32(&sm.tb.B[0][0][0]);

    int acc[8][8];
    #pragma unroll
    for (int i = 0; i < 8; i++)
        #pragma unroll
        for (int j = 0; j < 8; j++) acc[i][j] = 0;

    float d1[8];
    #pragma unroll
    for (int i = 0; i < 8; i++) d1[i] = 3.4e38f;

    // loader mapping: row = t>>1 (0..127), h = t&1
    int lrow = t >> 1, lh = t & 1;
    bool aval = (lrow < MTILE);
    int tokA = min(row0 + (aval ? lrow : 0), NTOK - 1);

    // prologue: chunk 0 (nt=0, kc=0) into buffer 0
    if (aval) cp16(sA + (uint32_t)((lh * MTILE + lrow) * 16),
                   Ab + (size_t)tokA * 128 + lh * 4);
    cp16(sB + (uint32_t)((lh * 128 + lrow) * 16),
         Bb + (size_t)lrow * 128 + lh * 4);
    CP_COMMIT();

    for (int g = 0; g < 128; ++g) {
        CP_WAIT0();
        __syncthreads();     // buf[g&1] complete and visible; other buf drained
        int buf = g & 1;

        if (g < 127) {       // issue async loads for chunk g+1 into the other buffer
            int ng = g + 1;
            int nt = ng >> 4, kc = ng & 15;
            int nb = ng & 1;
            if (aval) cp16(sA + (uint32_t)(((nb * 2 + lh) * MTILE + lrow) * 16),
                           Ab + (size_t)tokA * 128 + kc * 8 + lh * 4);
            cp16(sB + (uint32_t)(((nb * 2 + lh) * 128 + lrow) * 16),
                 Bb + (size_t)(nt * 128 + lrow) * 128 + kc * 8 + lh * 4);
            CP_COMMIT();
        }

        if (act) {
            #pragma unroll
            for (int h = 0; h < 2; ++h) {
                uint4 vb[8];
                #pragma unroll
                for (int j = 0; j < 8; j++) vb[j] = sm.tb.B[buf][h][tx + 16 * j];
                #pragma unroll
                for (int i = 0; i < 8; i++) {
                    uint4 va = sm.tb.A[buf][h][ty * 8 + i];
                    #pragma unroll
                    for (int j = 0; j < 8; j++) {
                        int s = acc[i][j];
                        s = __dp4a((int)va.x, (int)vb[j].x, s);
                        s = __dp4a((int)va.y, (int)vb[j].y, s);
                        s = __dp4a((int)va.z, (int)vb[j].z, s);
                        s = __dp4a((int)va.w, (int)vb[j].w, s);
                        acc[i][j] = s;
                    }
                }
            }

            if ((g & 15) == 15) {   // end of code tile: dists, fold min, reset
                int nt = g >> 4;
                int colb = nt * 128 + tx;
                float scf[8], cnf[8];
                #pragma unroll
                for (int j = 0; j < 8; j++) {
                    scf[j] = __ldg(scs + colb + 16 * j);
                    cnf[j] = __ldg(cn + colb + 16 * j);
                }
                #pragma unroll
                for (int i = 0; i < 8; i++) {
                    int row = row0 + ty * 8 + i;
                    float sri2 = 2.0f * __ldg(g_sr + min(row, NTOK - 1));
                    bool rok = (row < NTOK);
                    __half* dp = g_dist16 + (size_t)min(row, NTOK - 1) * KK_CB + colb;
                    #pragma unroll
                    for (int j = 0; j < 8; j++) {
                        float dd = cnf[j] - sri2 * scf[j] * (float)acc[i][j];
                        d1[i] = fminf(d1[i], dd);
                        acc[i][j] = 0;
                        if (rok) dp[16 * j] = __float2half(dd);
                    }
                }
            }
        }
    }

    __syncthreads();
    #pragma unroll
    for (int i = 0; i < 8; i++)
        if (act) sm.red.d[ty * 8 + i][tx] = d1[i];
    __syncthreads();
    if (t < MTILE) {
        float m = sm.red.d[t][0];
        #pragma unroll
        for (int j = 1; j < 16; j++) m = fminf(m, sm.red.d[t][j]);
        int tok = row0 + t;
        if (tok < NTOK) g_d1[tok] = m;
    }
}

// ---------------- fused rescue + residual update (lane-contiguous dims) ----------------
__global__ __launch_bounds__(256)
void rescue_update_kernel(const float* __restrict__ x,
                          const float* __restrict__ cb,
                          float* __restrict__ quant, int stage) {
    __shared__ float s_l[8];
    int warp = threadIdx.x >> 5, lane = threadIdx.x & 31;
    int tok  = blockIdx.x * 8 + warp;

    const __half* __restrict__ dist = g_dist16 + (size_t)tok * KK_CB;
    float thr = g_d1[tok] + MARGIN;

    const float* r = (stage == 0) ? (x + (size_t)tok * DD) : (g_residual + (size_t)tok * DD);
    float rv[16];
    #pragma unroll
    for (int i = 0; i < 4; ++i)
        *(float4*)(rv + 4 * i) = *(const float4*)(r + lane * 16 + 4 * i);

    const float* cbs = cb + (size_t)stage * KK_CB * DD;
    const float* cnp = g_cnorm + stage * KK_CB;

    float bd = 3.4e38f; int bk = 0;
    for (int j0 = 0; j0 < KK_CB; j0 += 32) {
        float dv = __half2float(dist[j0 + lane]);
        unsigned mask = __ballot_sync(0xffffffffu, dv <= thr);
        while (mask) {
            int j = j0 + __ffs(mask) - 1;
            mask &= mask - 1;
            const float* c = cbs + (size_t)j * DD + lane * 16;
            float s = 0.f;
            #pragma unroll
            for (int i = 0; i < 16; ++i) s += rv[i] * c[i];
            #pragma unroll
            for (int o = 16; o > 0; o >>= 1) s += __shfl_xor_sync(0xffffffffu, s, o);
            float de = __ldg(cnp + j) - 2.0f * s;
            if (de < bd) { bd = de; bk = j; }
        }
    }
    if (lane == 0) g_idx[stage * NTOK + tok] = bk;

    const float* c = cbs + (size_t)bk * DD + lane * 16;
    float nv[16];
    float lsum = 0.f, mx = 0.f;
    #pragma unroll
    for (int i = 0; i < 16; ++i) {
        nv[i] = rv[i] - c[i];
        lsum += nv[i] * nv[i];
        mx = fmaxf(mx, fabsf(nv[i]));
    }
    if (stage < QQ - 1) {
        float* res = g_residual + (size_t)tok * DD + lane * 16;
        #pragma unroll
        for (int i = 0; i < 4; ++i) *(float4*)(res + 4 * i) = *(float4*)(nv + 4 * i);
        #pragma unroll
        for (int o = 16; o > 0; o >>= 1) mx = fmaxf(mx, __shfl_xor_sync(0xffffffffu, mx, o));
        float sr = fmaxf(mx, 1e-20f) / 127.0f;
        float inv = 1.0f / sr;
        uint4 pk;
        pk.x = pack4(nv[0],  nv[1],  nv[2],  nv[3],  inv);
        pk.y = pack4(nv[4],  nv[5],  nv[6],  nv[7],  inv);
        pk.z = pack4(nv[8],  nv[9],  nv[10], nv[11], inv);
        pk.w = pack4(nv[12], nv[13], nv[14], nv[15], inv);
        *(uint4*)(g_r8 + (size_t)tok * 128 + lane * 4) = pk;
        if (lane == 0) g_sr[tok] = sr;
    } else {
        const float* xr = x + (size_t)tok * DD + lane * 16;
        float* q = quant + (size_t)tok * DD + lane * 16;
        #pragma unroll
        for (int i = 0; i < 16; ++i) q[i] = xr[i] - nv[i];
    }
    #pragma unroll
    for (int o = 16; o > 0; o >>= 1) lsum += __shfl_down_sync(0xffffffffu, lsum, o);
    if (lane == 0) s_l[warp] = lsum;
    __syncthreads();
    if (threadIdx.x == 0) {
        float s = 0.f;
        #pragma unroll
        for (int i = 0; i < 8; i++) s += s_l[i];
        atomicAdd(&g_loss, (double)s);
    }
}

// ---------------- gather + sum + GELU ----------------
__global__ __launch_bounds__(128)
void gather_gelu(float* __restrict__ y) {
    __shared__ int rows[20];
    int t = blockIdx.x;
    int b = t >> 11, to = t & (TOUT - 1);
    if (threadIdx.x < 20) {
        int kk = threadIdx.x >> 2, s = threadIdx.x & 3;
        int tin = 2 * to + kk - 1;
        rows[threadIdx.x] = ((unsigned)tin < (unsigned)TT)
            ? (kk * 4096 + s * 1024 + g_idx[s * NTOK + b * TT + tin]) : -1;
    }
    __syncthreads();
    int d4 = threadIdx.x;
    float ax = 0.f, ay = 0.f, az = 0.f, aw = 0.f;
    #pragma unroll
    for (int j = 0; j < 20; j++) {
        int r = rows[j];
        if (r >= 0) {
            float4 v = *(const float4*)(g_table + (size_t)r * DD + d4 * 4);
            ax += v.x; ay += v.y; az += v.z; aw += v.w;
        }
    }
    float4 o;
    o.x = 0.5f * ax * (1.0f + erff(ax * 0.70710678118654752f));
    o.y = 0.5f * ay * (1.0f + erff(ay * 0.70710678118654752f));
    o.z = 0.5f * az * (1.0f + erff(az * 0.70710678118654752f));
    o.w = 0.5f * aw * (1.0f + erff(aw * 0.70710678118654752f));
    *(float4*)(y + (size_t)t * DD + d4 * 4) = o;
}

// ---------------- indices (as float) + loss ----------------
__global__ void finalize_kernel(float* __restrict__ out) {
    int i = blockIdx.x * blockDim.x + threadIdx.x;
    if (i < IDX_SZ) out[Y_SZ + QO_SZ + i] = (float)g_idx[i];
    if (i == 0)     out[LOSS_OFF] = (float)(0.25 * g_loss / (double)NELEM);
}

// ---------------- launch ----------------
extern "C" void kernel_launch(void* const* d_in, const int* in_sizes, int n_in,
                              void* d_out, int out_size) {
    const float* x  = (const float*)d_in[0];
    const float* cb = (const float*)d_in[1];
    const float* w  = (const float*)d_in[2];
    float* out   = (float*)d_out;
    float* y     = out;
    float* quant = out + Y_SZ;

    quant_cb_kernel<<<(QQ * KK_CB * 32 + 255) / 256, 256>>>(cb);
    quant_x_kernel<<<(NTOK * 32 + 255) / 256, 256>>>(x);
    tableg_kernel<<<dim3(32, 4, 5), 256>>>(cb, w);

    for (int s = 0; s < QQ; ++s) {
        screen_kernel<<<NGRID, 256>>>(s);
        rescue_update_kernel<<<NTOK / 8, 256>>>(x, cb, quant, s);
    }
    gather_gelu<<<BB * TOUT, 128>>>(y);
    finalize_kernel<<<(IDX_SZ + 255) / 256, 256>>>(out);
}